// round 15
// baseline (speedup 1.0000x reference)
#include <cuda_runtime.h>
#include <cuda_bf16.h>
#include <cstddef>
#include <cstdint>

// ---------------- scratch ----------------
__device__ __align__(16) float g_a1t[96*55*55*64];    // conv1 out CHWN fp32
__device__ __align__(16) float g_a2t[256*27*27*64];   // conv2 out CHWN fp32
__device__ __align__(16) float g_a5t[256*13*13*64];   // conv5 out CHWN fp32
__device__ __align__(16) float g_p3[64*256*6*6];
__device__ __align__(16) float g_f1[64*4096];
__device__ __align__(16) float g_f2[64*4096];
__device__ __align__(16) float g_part[8*64*4096];
__device__ __align__(16) __nv_bfloat16 g_zero[64];

// CHWN split-bf16 activations
__device__ __align__(16) __nv_bfloat16 g_xc1h[3*227*227*64];
__device__ __align__(16) __nv_bfloat16 g_xc1l[3*227*227*64];
__device__ __align__(16) __nv_bfloat16 g_xt2h[96*31*32*64];
__device__ __align__(16) __nv_bfloat16 g_xt2l[96*31*32*64];
__device__ __align__(16) __nv_bfloat16 g_xt3h[256*15*16*64];
__device__ __align__(16) __nv_bfloat16 g_xt3l[256*15*16*64];
__device__ __align__(16) __nv_bfloat16 g_xt4h[384*15*16*64];
__device__ __align__(16) __nv_bfloat16 g_xt4l[384*15*16*64];
__device__ __align__(16) __nv_bfloat16 g_xt5h[384*15*16*64];
__device__ __align__(16) __nv_bfloat16 g_xt5l[384*15*16*64];
// pre-packed swizzled weight A-tiles
__device__ __align__(16) __nv_bfloat16 g_w1h[12*3072];   // conv1: [96co x 32k]
__device__ __align__(16) __nv_bfloat16 g_w1l[12*3072];
__device__ __align__(16) __nv_bfloat16 g_w2h[2*75*4096];
__device__ __align__(16) __nv_bfloat16 g_w2l[2*75*4096];
__device__ __align__(16) __nv_bfloat16 g_w3h[3*72*4096];
__device__ __align__(16) __nv_bfloat16 g_w3l[3*72*4096];
__device__ __align__(16) __nv_bfloat16 g_w4h[3*108*4096];
__device__ __align__(16) __nv_bfloat16 g_w4l[3*108*4096];
__device__ __align__(16) __nv_bfloat16 g_w5h[2*108*4096];
__device__ __align__(16) __nv_bfloat16 g_w5l[2*108*4096];

// ---------------- helpers ----------------
__device__ __forceinline__ uint32_t smem_u32(const void* p) {
    uint32_t a; asm("{ .reg .u64 t; cvta.to.shared.u64 t, %1; cvt.u32.u64 %0, t; }" : "=r"(a) : "l"(p)); return a;
}
__device__ __forceinline__ void mma_bf16(float* c, const unsigned* a, const unsigned* b) {
    asm volatile("mma.sync.aligned.m16n8k16.row.col.f32.bf16.bf16.f32 "
        "{%0,%1,%2,%3}, {%4,%5,%6,%7}, {%8,%9}, {%0,%1,%2,%3};"
        : "+f"(c[0]), "+f"(c[1]), "+f"(c[2]), "+f"(c[3])
        : "r"(a[0]), "r"(a[1]), "r"(a[2]), "r"(a[3]), "r"(b[0]), "r"(b[1]));
}
__device__ __forceinline__ void ldsm_x4(unsigned* r, uint32_t addr) {
    asm volatile("ldmatrix.sync.aligned.m8n8.x4.shared.b16 {%0,%1,%2,%3}, [%4];"
        : "=r"(r[0]), "=r"(r[1]), "=r"(r[2]), "=r"(r[3]) : "r"(addr));
}
__device__ __forceinline__ void ldsm_x2t(unsigned* r, uint32_t addr) {
    asm volatile("ldmatrix.sync.aligned.m8n8.x2.trans.shared.b16 {%0,%1}, [%2];"
        : "=r"(r[0]), "=r"(r[1]) : "r"(addr));
}
__device__ __forceinline__ uint32_t pack_bf(__nv_bfloat16 lo, __nv_bfloat16 hi) {
    return ((uint32_t)__bfloat16_as_ushort(hi) << 16) | __bfloat16_as_ushort(lo);
}
__device__ __forceinline__ void cp_async16(uint32_t dst, const void* src) {
    asm volatile("cp.async.cg.shared.global [%0], [%1], 16;" :: "r"(dst), "l"(src));
}
#define CP_COMMIT() asm volatile("cp.async.commit_group;" ::: "memory")
#define CP_WAIT1()  asm volatile("cp.async.wait_group 1;" ::: "memory")
__device__ __forceinline__ void fma2(unsigned long long &acc, unsigned long long a, unsigned long long b) {
    asm("fma.rn.f32x2 %0, %1, %2, %0;" : "+l"(acc) : "l"(a), "l"(b));
}
__device__ __forceinline__ unsigned long long pk2(float lo, float hi) {
    unsigned long long r; asm("mov.b64 %0, {%1, %2};" : "=l"(r) : "f"(lo), "f"(hi)); return r;
}
__device__ __forceinline__ void upk2(float &lo, float &hi, unsigned long long v) {
    asm("mov.b64 {%0, %1}, %2;" : "=f"(lo), "=f"(hi) : "l"(v));
}

// ================= mma conv v2 (stride-1): 2 px/CTA, 256 thr, 3-stage, 2 CTA/SM =================
// Ring of 3 x 32KB buffers: [0,8K) Ah | [8K,16K) Al | [16K+p*4K) Bh | [24K+p*4K) Bl
template<int CIN, int KS, int H, int PAD, int OUT_XT>
__global__ __launch_bounds__(256, 2) void mconv2(
    const __nv_bfloat16* __restrict__ xh, const __nv_bfloat16* __restrict__ xl,
    const __nv_bfloat16* __restrict__ wh, const __nv_bfloat16* __restrict__ wl,
    const float* __restrict__ bias,
    __nv_bfloat16* __restrict__ oxh, __nv_bfloat16* __restrict__ oxl,
    float* __restrict__ ofp)
{
    extern __shared__ __align__(16) char smem[];
    constexpr int HH = H + 2*PAD;
    constexpr int WP = ((HH + 15)/16)*16;
    constexpr int CB = CIN/32;
    constexpr int NKB = KS*KS*CB;
    constexpr int OWP = (H + 1)/2;

    const int tid = threadIdx.x;
    const int warp = tid >> 5, lane = tid & 31;
    const int wm = warp & 3, wn = warp >> 2;
    const int bx = blockIdx.x;
    const int oh = bx / OWP, ow0 = (bx % OWP)*2;
    const int npx = (ow0 + 1 < H) ? 2 : 1;
    const int cotile = blockIdx.y;
    const uint32_t sb = smem_u32(smem);

    const int sr = tid >> 3, su = tid & 7;
    const uint32_t brow = sr*128 + ((su*16) ^ ((sr & 7) << 4));

    auto stage = [&](int kb, int bb) {
        const uint32_t base = sb + bb*32768;
        const size_t wbase16 = ((size_t)(cotile*NKB + kb)) << 13;
        #pragma unroll
        for (int j = 0; j < 2; ++j) {
            const int c = tid + j*256;
            cp_async16(base + c*16,        (const char*)wh + wbase16 + c*16);
            cp_async16(base + 8192 + c*16, (const char*)wl + wbase16 + c*16);
        }
        const int tap = kb / CB, ci0 = (kb % CB)*32;
        const int kh = tap / KS, kw = tap % KS;
        #pragma unroll
        for (int p = 0; p < 2; ++p) {
            const int ow = (p < npx) ? (ow0 + p) : ow0;
            const size_t src = (((size_t)(ci0 + sr)*HH + oh + kh)*WP + ow + kw)*64 + su*8;
            cp_async16(base + 16384 + p*4096 + brow, xh + src);
            cp_async16(base + 24576 + p*4096 + brow, xl + src);
        }
    };

    float C[2][8][4];
    #pragma unroll
    for (int a = 0; a < 2; ++a)
        #pragma unroll
        for (int b = 0; b < 8; ++b)
            #pragma unroll
            for (int c = 0; c < 4; ++c) C[a][b][c] = 0.f;

    stage(0, 0); CP_COMMIT();
    if (NKB > 1) stage(1, 1);
    CP_COMMIT();

    int bcur = 0, bnext2 = 2;
    for (int kb = 0; kb < NKB; ++kb) {
        CP_WAIT1();
        __syncthreads();
        if (kb + 2 < NKB) stage(kb + 2, bnext2);
        CP_COMMIT();

        const uint32_t bA = sb + bcur*32768;
        const uint32_t bB = bA + 16384 + wn*4096;
        const int q = lane >> 3, rr = lane & 7;
        #pragma unroll
        for (int kc = 0; kc < 2; ++kc) {
            unsigned ah[2][4], al[2][4];
            #pragma unroll
            for (int mt = 0; mt < 2; ++mt) {
                const int row = wm*32 + mt*16 + (q & 1)*8 + rr;
                const uint32_t off = row*64 + ((kc*32 + (q >> 1)*16) ^ ((row & 3) << 4));
                ldsm_x4(ah[mt], bA + off);
                ldsm_x4(al[mt], bA + 8192 + off);
            }
            const int k = kc*16 + (lane & 15);
            #pragma unroll
            for (int nt = 0; nt < 8; ++nt) {
                unsigned bh[2], bl[2];
                const uint32_t off = k*128 + ((nt*16) ^ ((k & 7) << 4));
                ldsm_x2t(bh, bB + off);
                ldsm_x2t(bl, bB + 8192 + off);
                #pragma unroll
                for (int mt = 0; mt < 2; ++mt) {
                    mma_bf16(C[mt][nt], ah[mt], bh);
                    mma_bf16(C[mt][nt], ah[mt], bl);
                    mma_bf16(C[mt][nt], al[mt], bh);
                }
            }
        }
        bcur = (bcur == 2) ? 0 : bcur + 1;
        bnext2 = (bnext2 == 2) ? 0 : bnext2 + 1;
    }

    const int p = wn;
    if (p >= npx) return;
    const int ow = ow0 + p;
    const int g = lane >> 2, tg = lane & 3;
    #pragma unroll
    for (int mt = 0; mt < 2; ++mt) {
        #pragma unroll
        for (int hlf = 0; hlf < 2; ++hlf) {
            const int co = cotile*128 + wm*32 + mt*16 + hlf*8 + g;
            const float vb = bias[co] + 1.0f;
            #pragma unroll
            for (int nt = 0; nt < 8; ++nt) {
                const int n = nt*8 + tg*2;
                float v0 = C[mt][nt][hlf*2 + 0] + vb;
                float v1 = C[mt][nt][hlf*2 + 1] + vb;
                const float s0 = v0*v0, s1 = v1*v1;
                if (OUT_XT) {
                    const __nv_bfloat16 h0 = __float2bfloat16(s0);
                    const __nv_bfloat16 h1 = __float2bfloat16(s1);
                    const __nv_bfloat16 l0 = __float2bfloat16(s0 - __bfloat162float(h0));
                    const __nv_bfloat16 l1 = __float2bfloat16(s1 - __bfloat162float(h1));
                    const size_t o = (((size_t)co*HH + (oh + PAD))*WP + (ow + PAD))*64 + n;
                    *(uint32_t*)(oxh + o) = pack_bf(h0, h1);
                    *(uint32_t*)(oxl + o) = pack_bf(l0, l1);
                } else {
                    const size_t o = (((size_t)co*H + oh)*H + ow)*64 + n;
                    *(float2*)(ofp + o) = make_float2(s0, s1);
                }
            }
        }
    }
}

// ================= mma conv1: 96 co (no pad), 6 warps, 2 px/CTA, 3-stage =================
// Buffer (28KB): [0,6K) Ah | [6K,12K) Al | [12K+p*4K) Bh | [20K+p*4K) Bl ; ring stride 28672
__global__ __launch_bounds__(192, 2) void mconv1(
    const __nv_bfloat16* __restrict__ xh, const __nv_bfloat16* __restrict__ xl,
    const __nv_bfloat16* __restrict__ wh, const __nv_bfloat16* __restrict__ wl,
    const float* __restrict__ bias, const __nv_bfloat16* __restrict__ zbuf,
    float* __restrict__ ofp)
{
    extern __shared__ __align__(16) char smem[];
    constexpr int NKB = 12;

    const int tid = threadIdx.x;
    const int warp = tid >> 5, lane = tid & 31;
    const int wm = warp % 3, wn = warp / 3;
    const int bx = blockIdx.x;
    const int oh = bx / 28, ow0 = (bx % 28)*2;
    const int npx = (ow0 + 1 < 55) ? 2 : 1;
    const uint32_t sb = smem_u32(smem);

    auto stage = [&](int kb, int bb) {
        const uint32_t base = sb + bb*28672;
        const size_t wbase = (size_t)kb * 6144;   // bytes
        #pragma unroll
        for (int j = 0; j < 2; ++j) {
            const int c = tid + j*192;            // 0..383
            cp_async16(base + c*16,        (const char*)wh + wbase + c*16);
            cp_async16(base + 6144 + c*16, (const char*)wl + wbase + c*16);
        }
        const int kbase = kb*32;
        for (int c = tid; c < 512; c += 192) {
            const int p = c >> 8, r = c & 255;
            const int kk = r >> 3, u = r & 7;
            const int k = kbase + kk;
            const bool valid = k < 363;
            const int tap = k/3, ci = k%3;
            const int kh = tap/11, kw = tap%11;
            const int ow = (p < npx) ? (ow0 + p) : ow0;
            const __nv_bfloat16 *sh, *sl;
            if (valid) {
                const size_t src = (((size_t)ci*227 + oh*4 + kh)*227 + ow*4 + kw)*64 + u*8;
                sh = xh + src; sl = xl + src;
            } else { sh = zbuf + u*8; sl = zbuf + u*8; }
            const uint32_t dst = p*4096 + kk*128 + ((u*16) ^ ((kk & 7) << 4));
            cp_async16(base + 12288 + dst, sh);
            cp_async16(base + 20480 + dst, sl);
        }
    };

    float C[2][8][4];
    #pragma unroll
    for (int a = 0; a < 2; ++a)
        #pragma unroll
        for (int b = 0; b < 8; ++b)
            #pragma unroll
            for (int c = 0; c < 4; ++c) C[a][b][c] = 0.f;

    stage(0, 0); CP_COMMIT();
    stage(1, 1); CP_COMMIT();

    int bcur = 0, bnext2 = 2;
    for (int kb = 0; kb < NKB; ++kb) {
        CP_WAIT1();
        __syncthreads();
        if (kb + 2 < NKB) stage(kb + 2, bnext2);
        CP_COMMIT();

        const uint32_t bA = sb + bcur*28672;
        const uint32_t bB = bA + 12288 + wn*4096;
        const int q = lane >> 3, rr = lane & 7;
        #pragma unroll
        for (int kc = 0; kc < 2; ++kc) {
            unsigned ah[2][4], al[2][4];
            #pragma unroll
            for (int mt = 0; mt < 2; ++mt) {
                const int row = wm*32 + mt*16 + (q & 1)*8 + rr;
                const uint32_t off = row*64 + ((kc*32 + (q >> 1)*16) ^ ((row & 3) << 4));
                ldsm_x4(ah[mt], bA + off);
                ldsm_x4(al[mt], bA + 6144 + off);
            }
            const int k = kc*16 + (lane & 15);
            #pragma unroll
            for (int nt = 0; nt < 8; ++nt) {
                unsigned bh[2], bl[2];
                const uint32_t off = k*128 + ((nt*16) ^ ((k & 7) << 4));
                ldsm_x2t(bh, bB + off);
                ldsm_x2t(bl, bB + 8192 + off);
                #pragma unroll
                for (int mt = 0; mt < 2; ++mt) {
                    mma_bf16(C[mt][nt], ah[mt], bh);
                    mma_bf16(C[mt][nt], ah[mt], bl);
                    mma_bf16(C[mt][nt], al[mt], bh);
                }
            }
        }
        bcur = (bcur == 2) ? 0 : bcur + 1;
        bnext2 = (bnext2 == 2) ? 0 : bnext2 + 1;
    }

    const int p = wn;
    if (p >= npx) return;
    const int ow = ow0 + p;
    const int g = lane >> 2, tg = lane & 3;
    #pragma unroll
    for (int mt = 0; mt < 2; ++mt) {
        #pragma unroll
        for (int hlf = 0; hlf < 2; ++hlf) {
            const int co = wm*32 + mt*16 + hlf*8 + g;
            const float vb = bias[co] + 1.0f;
            #pragma unroll
            for (int nt = 0; nt < 8; ++nt) {
                const int n = nt*8 + tg*2;
                float v0 = C[mt][nt][hlf*2 + 0] + vb;
                float v1 = C[mt][nt][hlf*2 + 1] + vb;
                const size_t o = (((size_t)co*55 + oh)*55 + ow)*64 + n;
                *(float2*)(ofp + o) = make_float2(v0*v0, v1*v1);
            }
        }
    }
}

// ---------------- fused setup: chwn227 tiles + zero + weight prep ----------------
__device__ __forceinline__ void prep_generic(
    const float* __restrict__ w, __nv_bfloat16* __restrict__ dh, __nv_bfloat16* __restrict__ dl,
    int CIN, int KS2, int CB, int NKB, int idx)
{
    const int e = idx & 4095;
    const int kb = (idx >> 12) % NKB;
    const int cotile = idx / (NKB * 4096);
    const int co = e >> 5, kk = e & 31;
    const int tap = kb / CB;
    const int ci = (kb % CB)*32 + kk;
    const float val = w[((size_t)(cotile*128 + co)*CIN + ci)*KS2 + tap];
    const __nv_bfloat16 hv = __float2bfloat16(val);
    const __nv_bfloat16 lv = __float2bfloat16(val - __bfloat162float(hv));
    const size_t o = ((size_t)(cotile*NKB + kb) << 12) + co*32 + (kk ^ ((co & 3) << 3));
    dh[o] = hv; dl[o] = lv;
}

static constexpr int NB_CHWN = 1362;      // 3 ci * 227 ih * 2 halves
static constexpr int NB_ZERO = 2976;      // ceil(761856/256)
static constexpr int NPREP   = 36864 + (150+216+324+216)*4096;
static constexpr int NB_PREP = (NPREP + 255)/256;

__global__ __launch_bounds__(256) void setup_all(
    const float* __restrict__ x, __nv_bfloat16* __restrict__ c1h, __nv_bfloat16* __restrict__ c1l,
    uint4* za, uint4* zb4, uint4* zc, uint4* zd, uint4* ze, uint4* zf, uint4* zg, uint4* zh, uint4* zz,
    const float* __restrict__ w1, __nv_bfloat16* __restrict__ d1h, __nv_bfloat16* __restrict__ d1l,
    const float* __restrict__ w2, __nv_bfloat16* __restrict__ d2h, __nv_bfloat16* __restrict__ d2l,
    const float* __restrict__ w3, __nv_bfloat16* __restrict__ d3h, __nv_bfloat16* __restrict__ d3l,
    const float* __restrict__ w4, __nv_bfloat16* __restrict__ d4h, __nv_bfloat16* __restrict__ d4l,
    const float* __restrict__ w5, __nv_bfloat16* __restrict__ d5h, __nv_bfloat16* __restrict__ d5l)
{
    const int bx = blockIdx.x;
    const int tid = threadIdx.x;
    if (bx < NB_CHWN) {
        // input NCHW fp32 -> CHWN split-bf16, half-row tiles
        extern __shared__ float s[];   // [114][65]
        const int half = bx & 1;
        const int r = bx >> 1;
        const int ih = r % 227, ci = r / 227;
        const int off = half * 114;
        const int W = half ? 113 : 114;
        for (int i = tid; i < W*64; i += 256) {
            const int n = i / W, iw = i % W;
            s[iw*65 + n] = x[(((size_t)n*3 + ci)*227 + ih)*227 + off + iw];
        }
        __syncthreads();
        for (int i = tid; i < W*64; i += 256) {
            const int iw = i >> 6, n = i & 63;
            const float v = s[iw*65 + n];
            const __nv_bfloat16 hv = __float2bfloat16(v);
            const __nv_bfloat16 lv = __float2bfloat16(v - __bfloat162float(hv));
            const size_t o = (((size_t)ci*227 + ih)*227 + off + iw)*64 + n;
            c1h[o] = hv; c1l[o] = lv;
        }
        return;
    }
    if (bx < NB_CHWN + NB_ZERO) {
        const uint4 zv = make_uint4(0,0,0,0);
        const size_t idx = (size_t)(bx - NB_CHWN)*256 + tid;
        const size_t s2 = 761856, s3 = 491520, s4 = 737280;
        if (idx < s2) { za[idx] = zv; zb4[idx] = zv; }
        if (idx < s3) { zc[idx] = zv; zd[idx] = zv; }
        if (idx < s4) { ze[idx] = zv; zf[idx] = zv; zg[idx] = zv; zh[idx] = zv; }
        if (idx < 8)  { zz[idx] = zv; }
        return;
    }
    int idx = (bx - NB_CHWN - NB_ZERO)*256 + tid;
    if (idx >= NPREP) return;
    // conv1: 12 tiles of 3072 (96 co)
    if (idx < 36864) {
        const int e = idx % 3072, kb = idx / 3072;
        const int co = e >> 5, kk = e & 31;
        const int k = kb*32 + kk;
        float val = 0.f;
        if (k < 363) {
            const int tap = k/3, ci = k%3;
            val = w1[((size_t)(co*3 + ci)*11 + tap/11)*11 + tap%11];
        }
        const __nv_bfloat16 hv = __float2bfloat16(val);
        const __nv_bfloat16 lv = __float2bfloat16(val - __bfloat162float(hv));
        const size_t o = (size_t)kb*3072 + co*32 + (kk ^ ((co & 3) << 3));
        d1h[o] = hv; d1l[o] = lv;
        return;
    }
    idx -= 36864;
    if (idx < 150*4096) { prep_generic(w2, d2h, d2l,  96, 25,  3,  75, idx); return; }
    idx -= 150*4096;
    if (idx < 216*4096) { prep_generic(w3, d3h, d3l, 256,  9,  8,  72, idx); return; }
    idx -= 216*4096;
    if (idx < 324*4096) { prep_generic(w4, d4h, d4l, 384,  9, 12, 108, idx); return; }
    idx -= 324*4096;
    prep_generic(w5, d5h, d5l, 384,  9, 12, 108, idx);
}

// ---------------- pools (CHWN) ----------------
__global__ void pool1_chwn(const float* __restrict__ x, __nv_bfloat16* __restrict__ dh,
                           __nv_bfloat16* __restrict__ dl, int total)
{
    int idx = blockIdx.x * blockDim.x + threadIdx.x;
    if (idx >= total) return;
    const int n = idx & 63;
    int r = idx >> 6;
    const int ow = r % 27; r /= 27;
    const int oh = r % 27; r /= 27;
    const int co = r;
    float s = 0.f;
    #pragma unroll
    for (int i = 0; i < 3; ++i)
        #pragma unroll
        for (int j = 0; j < 3; ++j)
            s += x[(((size_t)co*55 + (oh*2 + i))*55 + (ow*2 + j))*64 + n];
    const float v = s * (1.0f/9.0f);
    const __nv_bfloat16 hv = __float2bfloat16(v);
    const __nv_bfloat16 lv = __float2bfloat16(v - __bfloat162float(hv));
    const size_t o = (((size_t)co*31 + oh + 2)*32 + ow + 2)*64 + n;
    dh[o] = hv; dl[o] = lv;
}

__global__ void pool2_chwn(const float* __restrict__ x, __nv_bfloat16* __restrict__ dh,
                           __nv_bfloat16* __restrict__ dl, int total)
{
    int idx = blockIdx.x * blockDim.x + threadIdx.x;
    if (idx >= total) return;
    const int n = idx & 63;
    int r = idx >> 6;
    const int ow = r % 13; r /= 13;
    const int oh = r % 13; r /= 13;
    const int co = r;
    float s = 0.f;
    #pragma unroll
    for (int i = 0; i < 3; ++i)
        #pragma unroll
        for (int j = 0; j < 3; ++j)
            s += x[(((size_t)co*27 + (oh*2 + i))*27 + (ow*2 + j))*64 + n];
    const float v = s * (1.0f/9.0f);
    const __nv_bfloat16 hv = __float2bfloat16(v);
    const __nv_bfloat16 lv = __float2bfloat16(v - __bfloat162float(hv));
    const size_t o = (((size_t)co*15 + oh + 1)*16 + ow + 1)*64 + n;
    dh[o] = hv; dl[o] = lv;
}

__global__ void pool3_chwn(const float* __restrict__ x, float* __restrict__ y, int total)
{
    int idx = blockIdx.x * blockDim.x + threadIdx.x;
    if (idx >= total) return;
    const int n = idx & 63;
    int r = idx >> 6;
    const int ow = r % 6; r /= 6;
    const int oh = r % 6; r /= 6;
    const int co = r;
    float s = 0.f;
    #pragma unroll
    for (int i = 0; i < 3; ++i)
        #pragma unroll
        for (int j = 0; j < 3; ++j)
            s += x[(((size_t)co*13 + (oh*2 + i))*13 + (ow*2 + j))*64 + n];
    y[(size_t)n*9216 + co*36 + oh*6 + ow] = s * (1.0f/9.0f);
}

// ---------------- FC ----------------
__global__ __launch_bounds__(128) void fc_big(
    const float* __restrict__ x, const float* __restrict__ w,
    float* __restrict__ part, int K, int N, int S)
{
    const int n = blockIdx.x*128 + threadIdx.x;
    const int s = blockIdx.z;
    const int kc = K / S;
    const int k0 = s*kc, k1 = k0 + kc;
    const int tid = threadIdx.x;

    __shared__ __align__(16) float xs[32][66];
    unsigned long long acc2[32];
    #pragma unroll
    for (int i = 0; i < 32; ++i) acc2[i] = 0ull;

    for (int kt = k0; kt < k1; kt += 32) {
        __syncthreads();
        for (int i = tid; i < 2048; i += 128) {
            const int kk = i & 31, m = i >> 5;
            xs[kk][m] = x[(size_t)m*K + kt + kk];
        }
        __syncthreads();
        if (n < N) {
            #pragma unroll 4
            for (int kk = 0; kk < 32; ++kk) {
                const float wv = w[(size_t)(kt + kk)*N + n];
                const unsigned long long wp = pk2(wv, wv);
                #pragma unroll
                for (int mp = 0; mp < 32; ++mp)
                    fma2(acc2[mp], *(const unsigned long long*)&xs[kk][2*mp], wp);
            }
        }
    }
    if (n < N) {
        #pragma unroll
        for (int mp = 0; mp < 32; ++mp) {
            float v0, v1;
            upk2(v0, v1, acc2[mp]);
            part[((size_t)s*64 + 2*mp    )*N + n] = v0;
            part[((size_t)s*64 + 2*mp + 1)*N + n] = v1;
        }
    }
}

__global__ void fc_reduce(const float* __restrict__ part, const float* __restrict__ bias,
                          float* __restrict__ out, int N, int S, int total)
{
    int idx = blockIdx.x*blockDim.x + threadIdx.x;
    if (idx >= total) return;
    int n = idx % N;
    float s = bias[n];
    for (int i = 0; i < S; ++i) s += part[(size_t)i*64*N + idx];
    out[idx] = s;
}

// ---------------- host launcher ----------------
extern "C" void kernel_launch(void* const* d_in, const int* in_sizes, int n_in,
                              void* d_out, int out_size)
{
    const float* x   = (const float*)d_in[0];
    const float* w1  = (const float*)d_in[1];
    const float* b1  = (const float*)d_in[2];
    const float* w2  = (const float*)d_in[3];
    const float* b2  = (const float*)d_in[4];
    const float* w3  = (const float*)d_in[5];
    const float* b3  = (const float*)d_in[6];
    const float* w4  = (const float*)d_in[7];
    const float* b4  = (const float*)d_in[8];
    const float* w5  = (const float*)d_in[9];
    const float* b5  = (const float*)d_in[10];
    const float* fw1 = (const float*)d_in[11];
    const float* fb1 = (const float*)d_in[12];
    const float* fw2 = (const float*)d_in[13];
    const float* fb2 = (const float*)d_in[14];
    const float* fw3 = (const float*)d_in[15];
    const float* fb3 = (const float*)d_in[16];
    float* out = (float*)d_out;

    float *a1t,*a2t,*a5t,*p3,*f1,*f2,*part;
    __nv_bfloat16 *zb,*xc1h,*xc1l,*xt2h,*xt2l,*xt3h,*xt3l,*xt4h,*xt4l,*xt5h,*xt5l;
    __nv_bfloat16 *w1h,*w1l,*w2h,*w2l,*w3h,*w3l,*w4h,*w4l,*w5h,*w5l;
    cudaGetSymbolAddress((void**)&a1t, g_a1t);
    cudaGetSymbolAddress((void**)&a2t, g_a2t);
    cudaGetSymbolAddress((void**)&a5t, g_a5t);
    cudaGetSymbolAddress((void**)&p3, g_p3);
    cudaGetSymbolAddress((void**)&f1, g_f1);
    cudaGetSymbolAddress((void**)&f2, g_f2);
    cudaGetSymbolAddress((void**)&part, g_part);
    cudaGetSymbolAddress((void**)&zb, g_zero);
    cudaGetSymbolAddress((void**)&xc1h, g_xc1h);
    cudaGetSymbolAddress((void**)&xc1l, g_xc1l);
    cudaGetSymbolAddress((void**)&xt2h, g_xt2h);
    cudaGetSymbolAddress((void**)&xt2l, g_xt2l);
    cudaGetSymbolAddress((void**)&xt3h, g_xt3h);
    cudaGetSymbolAddress((void**)&xt3l, g_xt3l);
    cudaGetSymbolAddress((void**)&xt4h, g_xt4h);
    cudaGetSymbolAddress((void**)&xt4l, g_xt4l);
    cudaGetSymbolAddress((void**)&xt5h, g_xt5h);
    cudaGetSymbolAddress((void**)&xt5l, g_xt5l);
    cudaGetSymbolAddress((void**)&w1h, g_w1h);
    cudaGetSymbolAddress((void**)&w1l, g_w1l);
    cudaGetSymbolAddress((void**)&w2h, g_w2h);
    cudaGetSymbolAddress((void**)&w2l, g_w2l);
    cudaGetSymbolAddress((void**)&w3h, g_w3h);
    cudaGetSymbolAddress((void**)&w3l, g_w3l);
    cudaGetSymbolAddress((void**)&w4h, g_w4h);
    cudaGetSymbolAddress((void**)&w4l, g_w4l);
    cudaGetSymbolAddress((void**)&w5h, g_w5h);
    cudaGetSymbolAddress((void**)&w5l, g_w5l);

    cudaFuncSetAttribute(mconv1,               cudaFuncAttributeMaxDynamicSharedMemorySize, 86016);
    cudaFuncSetAttribute(mconv2<96,5,27,2,0>,  cudaFuncAttributeMaxDynamicSharedMemorySize, 98304);
    cudaFuncSetAttribute(mconv2<256,3,13,1,1>, cudaFuncAttributeMaxDynamicSharedMemorySize, 98304);
    cudaFuncSetAttribute(mconv2<384,3,13,1,1>, cudaFuncAttributeMaxDynamicSharedMemorySize, 98304);
    cudaFuncSetAttribute(mconv2<384,3,13,1,0>, cudaFuncAttributeMaxDynamicSharedMemorySize, 98304);

    // 1: fused setup (chwn + zero + prep)
    setup_all<<<NB_CHWN + NB_ZERO + NB_PREP, 256, 114*65*4>>>(
        x, xc1h, xc1l,
        (uint4*)xt2h, (uint4*)xt2l, (uint4*)xt3h, (uint4*)xt3l,
        (uint4*)xt4h, (uint4*)xt4l, (uint4*)xt5h, (uint4*)xt5l, (uint4*)zb,
        w1, w1h, w1l, w2, w2h, w2l, w3, w3h, w3l, w4, w4h, w4l, w5, w5h, w5l);
    // 2: conv1 (mma, 96co)
    mconv1<<<dim3(55*28), 192, 86016>>>(xc1h, xc1l, w1h, w1l, b1, zb, a1t);
    // 3: pool1
    { int t = 96*27*27*64; pool1_chwn<<<(t+255)/256, 256>>>(a1t, xt2h, xt2l, t); }
    // 4: conv2 (mma)  <-- profiled launch
    mconv2<96,5,27,2,0><<<dim3(27*14, 2), 256, 98304>>>(xt2h, xt2l, w2h, w2l, b2, nullptr, nullptr, a2t);
    // 5: pool2
    { int t = 256*13*13*64; pool2_chwn<<<(t+255)/256, 256>>>(a2t, xt3h, xt3l, t); }
    // conv3/4/5
    mconv2<256,3,13,1,1><<<dim3(13*7, 3), 256, 98304>>>(xt3h, xt3l, w3h, w3l, b3, xt4h, xt4l, nullptr);
    mconv2<384,3,13,1,1><<<dim3(13*7, 3), 256, 98304>>>(xt4h, xt4l, w4h, w4l, b4, xt5h, xt5l, nullptr);
    mconv2<384,3,13,1,0><<<dim3(13*7, 2), 256, 98304>>>(xt5h, xt5l, w5h, w5l, b5, nullptr, nullptr, a5t);
    // pool3
    { int t = 64*256*36; pool3_chwn<<<(t+255)/256, 256>>>(a5t, p3, t); }

    // FC
    fc_big<<<dim3(32, 1, 8), 128>>>(p3, fw1, part, 9216, 4096, 8);
    fc_reduce<<<(64*4096 + 255)/256, 256>>>(part, fb1, f1, 4096, 8, 64*4096);
    fc_big<<<dim3(32, 1, 8), 128>>>(f1, fw2, part, 4096, 4096, 8);
    fc_reduce<<<(64*4096 + 255)/256, 256>>>(part, fb2, f2, 4096, 8, 64*4096);
    fc_big<<<dim3(8, 1, 8), 128>>>(f2, fw3, part, 4096, 1000, 8);
    fc_reduce<<<(64*1000 + 255)/256, 256>>>(part, fb3, out, 1000, 8, 64*1000);
}

// round 16
// speedup vs baseline: 1.4404x; 1.4404x over previous
#include <cuda_runtime.h>
#include <cuda_bf16.h>
#include <cstddef>
#include <cstdint>

// ---------------- scratch ----------------
__device__ __align__(16) float g_a1t[96*55*55*64];    // conv1 out CHWN fp32
__device__ __align__(16) float g_a2t[256*27*27*64];   // conv2 out CHWN fp32
__device__ __align__(16) float g_a5t[256*13*13*64];   // conv5 out CHWN fp32
__device__ __align__(16) float g_p3[64*256*6*6];
__device__ __align__(16) float g_f1[64*4096];
__device__ __align__(16) float g_f2[64*4096];
__device__ __align__(16) float g_part[8*64*4096];
__device__ __align__(16) __nv_bfloat16 g_zero[64];

// CHWN split-bf16 activations
__device__ __align__(16) __nv_bfloat16 g_xc1h[3*227*227*64];
__device__ __align__(16) __nv_bfloat16 g_xc1l[3*227*227*64];
__device__ __align__(16) __nv_bfloat16 g_xt2h[96*31*32*64];
__device__ __align__(16) __nv_bfloat16 g_xt2l[96*31*32*64];
__device__ __align__(16) __nv_bfloat16 g_xt3h[256*15*16*64];
__device__ __align__(16) __nv_bfloat16 g_xt3l[256*15*16*64];
__device__ __align__(16) __nv_bfloat16 g_xt4h[384*15*16*64];
__device__ __align__(16) __nv_bfloat16 g_xt4l[384*15*16*64];
__device__ __align__(16) __nv_bfloat16 g_xt5h[384*15*16*64];
__device__ __align__(16) __nv_bfloat16 g_xt5l[384*15*16*64];
// pre-packed swizzled weight A-tiles
__device__ __align__(16) __nv_bfloat16 g_w1h[12*3072];   // conv1: [96co x 32k]
__device__ __align__(16) __nv_bfloat16 g_w1l[12*3072];
__device__ __align__(16) __nv_bfloat16 g_w2h[2*75*4096];
__device__ __align__(16) __nv_bfloat16 g_w2l[2*75*4096];
__device__ __align__(16) __nv_bfloat16 g_w3h[3*72*4096];
__device__ __align__(16) __nv_bfloat16 g_w3l[3*72*4096];
__device__ __align__(16) __nv_bfloat16 g_w4h[3*108*4096];
__device__ __align__(16) __nv_bfloat16 g_w4l[3*108*4096];
__device__ __align__(16) __nv_bfloat16 g_w5h[2*108*4096];
__device__ __align__(16) __nv_bfloat16 g_w5l[2*108*4096];

// ---------------- helpers ----------------
__device__ __forceinline__ uint32_t smem_u32(const void* p) {
    uint32_t a; asm("{ .reg .u64 t; cvta.to.shared.u64 t, %1; cvt.u32.u64 %0, t; }" : "=r"(a) : "l"(p)); return a;
}
__device__ __forceinline__ void mma_bf16(float* c, const unsigned* a, const unsigned* b) {
    asm volatile("mma.sync.aligned.m16n8k16.row.col.f32.bf16.bf16.f32 "
        "{%0,%1,%2,%3}, {%4,%5,%6,%7}, {%8,%9}, {%0,%1,%2,%3};"
        : "+f"(c[0]), "+f"(c[1]), "+f"(c[2]), "+f"(c[3])
        : "r"(a[0]), "r"(a[1]), "r"(a[2]), "r"(a[3]), "r"(b[0]), "r"(b[1]));
}
__device__ __forceinline__ void ldsm_x4(unsigned* r, uint32_t addr) {
    asm volatile("ldmatrix.sync.aligned.m8n8.x4.shared.b16 {%0,%1,%2,%3}, [%4];"
        : "=r"(r[0]), "=r"(r[1]), "=r"(r[2]), "=r"(r[3]) : "r"(addr));
}
__device__ __forceinline__ void ldsm_x2t(unsigned* r, uint32_t addr) {
    asm volatile("ldmatrix.sync.aligned.m8n8.x2.trans.shared.b16 {%0,%1}, [%2];"
        : "=r"(r[0]), "=r"(r[1]) : "r"(addr));
}
__device__ __forceinline__ uint32_t pack_bf(__nv_bfloat16 lo, __nv_bfloat16 hi) {
    return ((uint32_t)__bfloat16_as_ushort(hi) << 16) | __bfloat16_as_ushort(lo);
}
__device__ __forceinline__ void cp_async16(uint32_t dst, const void* src) {
    asm volatile("cp.async.cg.shared.global [%0], [%1], 16;" :: "r"(dst), "l"(src));
}
#define CP_COMMIT() asm volatile("cp.async.commit_group;" ::: "memory")
#define CP_WAIT1()  asm volatile("cp.async.wait_group 1;" ::: "memory")
__device__ __forceinline__ void fma2(unsigned long long &acc, unsigned long long a, unsigned long long b) {
    asm("fma.rn.f32x2 %0, %1, %2, %0;" : "+l"(acc) : "l"(a), "l"(b));
}
__device__ __forceinline__ unsigned long long pk2(float lo, float hi) {
    unsigned long long r; asm("mov.b64 %0, {%1, %2};" : "=l"(r) : "f"(lo), "f"(hi)); return r;
}
__device__ __forceinline__ void upk2(float &lo, float &hi, unsigned long long v) {
    asm("mov.b64 {%0, %1}, %2;" : "=f"(lo), "=f"(hi) : "l"(v));
}
__device__ __forceinline__ void split2(float v0, float v1, uint32_t &ph, uint32_t &pl) {
    const __nv_bfloat16 h0 = __float2bfloat16(v0);
    const __nv_bfloat16 h1 = __float2bfloat16(v1);
    const __nv_bfloat16 l0 = __float2bfloat16(v0 - __bfloat162float(h0));
    const __nv_bfloat16 l1 = __float2bfloat16(v1 - __bfloat162float(h1));
    ph = pack_bf(h0, h1); pl = pack_bf(l0, l1);
}

// ================= mma conv v2 (stride-1): 2 px/CTA, 256 thr, 3-stage, 2 CTA/SM =================
template<int CIN, int KS, int H, int PAD, int OUT_XT>
__global__ __launch_bounds__(256, 2) void mconv2(
    const __nv_bfloat16* __restrict__ xh, const __nv_bfloat16* __restrict__ xl,
    const __nv_bfloat16* __restrict__ wh, const __nv_bfloat16* __restrict__ wl,
    const float* __restrict__ bias,
    __nv_bfloat16* __restrict__ oxh, __nv_bfloat16* __restrict__ oxl,
    float* __restrict__ ofp)
{
    extern __shared__ __align__(16) char smem[];
    constexpr int HH = H + 2*PAD;
    constexpr int WP = ((HH + 15)/16)*16;
    constexpr int CB = CIN/32;
    constexpr int NKB = KS*KS*CB;
    constexpr int OWP = (H + 1)/2;

    const int tid = threadIdx.x;
    const int warp = tid >> 5, lane = tid & 31;
    const int wm = warp & 3, wn = warp >> 2;
    const int bx = blockIdx.x;
    const int oh = bx / OWP, ow0 = (bx % OWP)*2;
    const int npx = (ow0 + 1 < H) ? 2 : 1;
    const int cotile = blockIdx.y;
    const uint32_t sb = smem_u32(smem);

    const int sr = tid >> 3, su = tid & 7;
    const uint32_t brow = sr*128 + ((su*16) ^ ((sr & 7) << 4));

    auto stage = [&](int kb, int bb) {
        const uint32_t base = sb + bb*32768;
        const size_t wbase16 = ((size_t)(cotile*NKB + kb)) << 13;
        #pragma unroll
        for (int j = 0; j < 2; ++j) {
            const int c = tid + j*256;
            cp_async16(base + c*16,        (const char*)wh + wbase16 + c*16);
            cp_async16(base + 8192 + c*16, (const char*)wl + wbase16 + c*16);
        }
        const int tap = kb / CB, ci0 = (kb % CB)*32;
        const int kh = tap / KS, kw = tap % KS;
        #pragma unroll
        for (int p = 0; p < 2; ++p) {
            const int ow = (p < npx) ? (ow0 + p) : ow0;
            const size_t src = (((size_t)(ci0 + sr)*HH + oh + kh)*WP + ow + kw)*64 + su*8;
            cp_async16(base + 16384 + p*4096 + brow, xh + src);
            cp_async16(base + 24576 + p*4096 + brow, xl + src);
        }
    };

    float C[2][8][4];
    #pragma unroll
    for (int a = 0; a < 2; ++a)
        #pragma unroll
        for (int b = 0; b < 8; ++b)
            #pragma unroll
            for (int c = 0; c < 4; ++c) C[a][b][c] = 0.f;

    stage(0, 0); CP_COMMIT();
    if (NKB > 1) stage(1, 1);
    CP_COMMIT();

    int bcur = 0, bnext2 = 2;
    for (int kb = 0; kb < NKB; ++kb) {
        CP_WAIT1();
        __syncthreads();
        if (kb + 2 < NKB) stage(kb + 2, bnext2);
        CP_COMMIT();

        const uint32_t bA = sb + bcur*32768;
        const uint32_t bB = bA + 16384 + wn*4096;
        const int q = lane >> 3, rr = lane & 7;
        #pragma unroll
        for (int kc = 0; kc < 2; ++kc) {
            unsigned ah[2][4], al[2][4];
            #pragma unroll
            for (int mt = 0; mt < 2; ++mt) {
                const int row = wm*32 + mt*16 + (q & 1)*8 + rr;
                const uint32_t off = row*64 + ((kc*32 + (q >> 1)*16) ^ ((row & 3) << 4));
                ldsm_x4(ah[mt], bA + off);
                ldsm_x4(al[mt], bA + 8192 + off);
            }
            const int k = kc*16 + (lane & 15);
            #pragma unroll
            for (int nt = 0; nt < 8; ++nt) {
                unsigned bh[2], bl[2];
                const uint32_t off = k*128 + ((nt*16) ^ ((k & 7) << 4));
                ldsm_x2t(bh, bB + off);
                ldsm_x2t(bl, bB + 8192 + off);
                #pragma unroll
                for (int mt = 0; mt < 2; ++mt) {
                    mma_bf16(C[mt][nt], ah[mt], bh);
                    mma_bf16(C[mt][nt], ah[mt], bl);
                    mma_bf16(C[mt][nt], al[mt], bh);
                }
            }
        }
        bcur = (bcur == 2) ? 0 : bcur + 1;
        bnext2 = (bnext2 == 2) ? 0 : bnext2 + 1;
    }

    const int p = wn;
    if (p >= npx) return;
    const int ow = ow0 + p;
    const int g = lane >> 2, tg = lane & 3;
    #pragma unroll
    for (int mt = 0; mt < 2; ++mt) {
        #pragma unroll
        for (int hlf = 0; hlf < 2; ++hlf) {
            const int co = cotile*128 + wm*32 + mt*16 + hlf*8 + g;
            const float vb = bias[co] + 1.0f;
            #pragma unroll
            for (int nt = 0; nt < 8; ++nt) {
                const int n = nt*8 + tg*2;
                float v0 = C[mt][nt][hlf*2 + 0] + vb;
                float v1 = C[mt][nt][hlf*2 + 1] + vb;
                const float s0 = v0*v0, s1 = v1*v1;
                if (OUT_XT) {
                    uint32_t ph, pl;
                    split2(s0, s1, ph, pl);
                    const size_t o = (((size_t)co*HH + (oh + PAD))*WP + (ow + PAD))*64 + n;
                    *(uint32_t*)(oxh + o) = ph;
                    *(uint32_t*)(oxl + o) = pl;
                } else {
                    const size_t o = (((size_t)co*H + oh)*H + ow)*64 + n;
                    *(float2*)(ofp + o) = make_float2(s0, s1);
                }
            }
        }
    }
}

// ================= mma conv1: 96 co, 6 warps, 2 px/CTA, 3-stage =================
__global__ __launch_bounds__(192, 2) void mconv1(
    const __nv_bfloat16* __restrict__ xh, const __nv_bfloat16* __restrict__ xl,
    const __nv_bfloat16* __restrict__ wh, const __nv_bfloat16* __restrict__ wl,
    const float* __restrict__ bias, const __nv_bfloat16* __restrict__ zbuf,
    float* __restrict__ ofp)
{
    extern __shared__ __align__(16) char smem[];
    constexpr int NKB = 12;

    const int tid = threadIdx.x;
    const int warp = tid >> 5, lane = tid & 31;
    const int wm = warp % 3, wn = warp / 3;
    const int bx = blockIdx.x;
    const int oh = bx / 28, ow0 = (bx % 28)*2;
    const int npx = (ow0 + 1 < 55) ? 2 : 1;
    const uint32_t sb = smem_u32(smem);

    auto stage = [&](int kb, int bb) {
        const uint32_t base = sb + bb*28672;
        const size_t wbase = (size_t)kb * 6144;
        #pragma unroll
        for (int j = 0; j < 2; ++j) {
            const int c = tid + j*192;
            cp_async16(base + c*16,        (const char*)wh + wbase + c*16);
            cp_async16(base + 6144 + c*16, (const char*)wl + wbase + c*16);
        }
        const int kbase = kb*32;
        for (int c = tid; c < 512; c += 192) {
            const int p = c >> 8, r = c & 255;
            const int kk = r >> 3, u = r & 7;
            const int k = kbase + kk;
            const bool valid = k < 363;
            const int tap = k/3, ci = k%3;
            const int kh = tap/11, kw = tap%11;
            const int ow = (p < npx) ? (ow0 + p) : ow0;
            const __nv_bfloat16 *sh, *sl;
            if (valid) {
                const size_t src = (((size_t)ci*227 + oh*4 + kh)*227 + ow*4 + kw)*64 + u*8;
                sh = xh + src; sl = xl + src;
            } else { sh = zbuf + u*8; sl = zbuf + u*8; }
            const uint32_t dst = p*4096 + kk*128 + ((u*16) ^ ((kk & 7) << 4));
            cp_async16(base + 12288 + dst, sh);
            cp_async16(base + 20480 + dst, sl);
        }
    };

    float C[2][8][4];
    #pragma unroll
    for (int a = 0; a < 2; ++a)
        #pragma unroll
        for (int b = 0; b < 8; ++b)
            #pragma unroll
            for (int c = 0; c < 4; ++c) C[a][b][c] = 0.f;

    stage(0, 0); CP_COMMIT();
    stage(1, 1); CP_COMMIT();

    int bcur = 0, bnext2 = 2;
    for (int kb = 0; kb < NKB; ++kb) {
        CP_WAIT1();
        __syncthreads();
        if (kb + 2 < NKB) stage(kb + 2, bnext2);
        CP_COMMIT();

        const uint32_t bA = sb + bcur*28672;
        const uint32_t bB = bA + 12288 + wn*4096;
        const int q = lane >> 3, rr = lane & 7;
        #pragma unroll
        for (int kc = 0; kc < 2; ++kc) {
            unsigned ah[2][4], al[2][4];
            #pragma unroll
            for (int mt = 0; mt < 2; ++mt) {
                const int row = wm*32 + mt*16 + (q & 1)*8 + rr;
                const uint32_t off = row*64 + ((kc*32 + (q >> 1)*16) ^ ((row & 3) << 4));
                ldsm_x4(ah[mt], bA + off);
                ldsm_x4(al[mt], bA + 6144 + off);
            }
            const int k = kc*16 + (lane & 15);
            #pragma unroll
            for (int nt = 0; nt < 8; ++nt) {
                unsigned bh[2], bl[2];
                const uint32_t off = k*128 + ((nt*16) ^ ((k & 7) << 4));
                ldsm_x2t(bh, bB + off);
                ldsm_x2t(bl, bB + 8192 + off);
                #pragma unroll
                for (int mt = 0; mt < 2; ++mt) {
                    mma_bf16(C[mt][nt], ah[mt], bh);
                    mma_bf16(C[mt][nt], ah[mt], bl);
                    mma_bf16(C[mt][nt], al[mt], bh);
                }
            }
        }
        bcur = (bcur == 2) ? 0 : bcur + 1;
        bnext2 = (bnext2 == 2) ? 0 : bnext2 + 1;
    }

    const int p = wn;
    if (p >= npx) return;
    const int ow = ow0 + p;
    const int g = lane >> 2, tg = lane & 3;
    #pragma unroll
    for (int mt = 0; mt < 2; ++mt) {
        #pragma unroll
        for (int hlf = 0; hlf < 2; ++hlf) {
            const int co = wm*32 + mt*16 + hlf*8 + g;
            const float vb = bias[co] + 1.0f;
            #pragma unroll
            for (int nt = 0; nt < 8; ++nt) {
                const int n = nt*8 + tg*2;
                float v0 = C[mt][nt][hlf*2 + 0] + vb;
                float v1 = C[mt][nt][hlf*2 + 1] + vb;
                const size_t o = (((size_t)co*55 + oh)*55 + ow)*64 + n;
                *(float2*)(ofp + o) = make_float2(v0*v0, v1*v1);
            }
        }
    }
}

// ================= FC via mma: C[64m x 128n] per CTA, K/S split, fp32->split-bf16 on the fly =================
// smem 24KB: Ah [0,4K) | Al [4K,8K) | Bh [8K,16K) | Bl [16K,24K)
__global__ __launch_bounds__(256, 2) void fc_mma(
    const float* __restrict__ x, const float* __restrict__ w,
    float* __restrict__ part, int K, int N, int S)
{
    __shared__ __align__(16) char smem[24576];
    const int tid = threadIdx.x;
    const int warp = tid >> 5, lane = tid & 31;
    const int wm = warp & 3, wn = warp >> 2;
    const int n0 = blockIdx.x * 128;
    const int s = blockIdx.y;
    const int kc = K / S;
    const int k0 = s * kc;
    const int nkb = kc / 32;
    const uint32_t sb = smem_u32(smem);

    const int am = tid >> 2, ak8 = (tid & 3) * 8;
    const int bk = tid >> 3, bch = tid & 7;

    const uint32_t adst = (uint32_t)(am * 64) + (((uint32_t)(ak8 * 2)) ^ ((am & 3) << 4));
    const uint32_t bbase = 8192u + (bch >> 2) * 4096u + bk * 128u;
    const uint32_t bsw0 = ((uint32_t)((bch & 3) * 32))      ^ ((bk & 7) << 4);
    const uint32_t bsw1 = ((uint32_t)((bch & 3) * 32 + 16)) ^ ((bk & 7) << 4);

    float xr[8], wr[16];
    {
        const float* xp = x + (size_t)am * K + k0 + ak8;
        #pragma unroll
        for (int j = 0; j < 8; ++j) xr[j] = xp[j];
        const float* wp = w + (size_t)(k0 + bk) * N + n0 + bch * 16;
        #pragma unroll
        for (int j = 0; j < 16; ++j) wr[j] = wp[j];
    }

    float C[8][4];
    #pragma unroll
    for (int b = 0; b < 8; ++b)
        #pragma unroll
        for (int c = 0; c < 4; ++c) C[b][c] = 0.f;

    for (int kb = 0; kb < nkb; ++kb) {
        __syncthreads();
        // convert + store tiles
        {
            uint32_t ph[4], pl[4];
            #pragma unroll
            for (int j = 0; j < 4; ++j) split2(xr[2*j], xr[2*j+1], ph[j], pl[j]);
            *(uint4*)(smem + adst)        = *(const uint4*)ph;
            *(uint4*)(smem + 4096 + adst) = *(const uint4*)pl;
            uint32_t qh[8], ql[8];
            #pragma unroll
            for (int j = 0; j < 8; ++j) split2(wr[2*j], wr[2*j+1], qh[j], ql[j]);
            *(uint4*)(smem + bbase + bsw0)         = *(const uint4*)qh;
            *(uint4*)(smem + bbase + bsw1)         = *(const uint4*)(qh + 4);
            *(uint4*)(smem + 8192 + bbase + bsw0)  = *(const uint4*)ql;
            *(uint4*)(smem + 8192 + bbase + bsw1)  = *(const uint4*)(ql + 4);
        }
        __syncthreads();
        if (kb + 1 < nkb) {
            const int kt = k0 + (kb + 1) * 32;
            const float* xp = x + (size_t)am * K + kt + ak8;
            #pragma unroll
            for (int j = 0; j < 8; ++j) xr[j] = xp[j];
            const float* wp = w + (size_t)(kt + bk) * N + n0 + bch * 16;
            #pragma unroll
            for (int j = 0; j < 16; ++j) wr[j] = wp[j];
        }
        const int q = lane >> 3, rr = lane & 7;
        #pragma unroll
        for (int kk = 0; kk < 2; ++kk) {
            unsigned ah[4], al[4];
            const int row = wm*16 + (q & 1)*8 + rr;
            const uint32_t off = row*64 + ((kk*32 + (q >> 1)*16) ^ ((row & 3) << 4));
            ldsm_x4(ah, sb + off);
            ldsm_x4(al, sb + 4096 + off);
            const int k = kk*16 + (lane & 15);
            #pragma unroll
            for (int nt = 0; nt < 8; ++nt) {
                unsigned bh[2], bl[2];
                const uint32_t off2 = k*128 + ((nt*16) ^ ((k & 7) << 4));
                ldsm_x2t(bh, sb + 8192 + wn*4096 + off2);
                ldsm_x2t(bl, sb + 16384 + wn*4096 + off2);
                mma_bf16(C[nt], ah, bh);
                mma_bf16(C[nt], ah, bl);
                mma_bf16(C[nt], al, bh);
            }
        }
    }

    const int g = lane >> 2, tg = lane & 3;
    #pragma unroll
    for (int hlf = 0; hlf < 2; ++hlf) {
        const int m = wm*16 + hlf*8 + g;
        #pragma unroll
        for (int nt = 0; nt < 8; ++nt) {
            const int n = wn*64 + nt*8 + tg*2;
            *(float2*)(part + ((size_t)s*64 + m)*N + n0 + n) =
                make_float2(C[nt][hlf*2], C[nt][hlf*2 + 1]);
        }
    }
}

// ---------------- fused setup: chwn227 tiles + zero + weight prep ----------------
__device__ __forceinline__ void prep_generic(
    const float* __restrict__ w, __nv_bfloat16* __restrict__ dh, __nv_bfloat16* __restrict__ dl,
    int CIN, int KS2, int CB, int NKB, int idx)
{
    const int e = idx & 4095;
    const int kb = (idx >> 12) % NKB;
    const int cotile = idx / (NKB * 4096);
    const int co = e >> 5, kk = e & 31;
    const int tap = kb / CB;
    const int ci = (kb % CB)*32 + kk;
    const float val = w[((size_t)(cotile*128 + co)*CIN + ci)*KS2 + tap];
    const __nv_bfloat16 hv = __float2bfloat16(val);
    const __nv_bfloat16 lv = __float2bfloat16(val - __bfloat162float(hv));
    const size_t o = ((size_t)(cotile*NKB + kb) << 12) + co*32 + (kk ^ ((co & 3) << 3));
    dh[o] = hv; dl[o] = lv;
}

static constexpr int NB_CHWN = 1362;
static constexpr int NB_ZERO = 2976;
static constexpr int NPREP   = 36864 + (150+216+324+216)*4096;
static constexpr int NB_PREP = (NPREP + 255)/256;

__global__ __launch_bounds__(256) void setup_all(
    const float* __restrict__ x, __nv_bfloat16* __restrict__ c1h, __nv_bfloat16* __restrict__ c1l,
    uint4* za, uint4* zb4, uint4* zc, uint4* zd, uint4* ze, uint4* zf, uint4* zg, uint4* zh, uint4* zz,
    const float* __restrict__ w1, __nv_bfloat16* __restrict__ d1h, __nv_bfloat16* __restrict__ d1l,
    const float* __restrict__ w2, __nv_bfloat16* __restrict__ d2h, __nv_bfloat16* __restrict__ d2l,
    const float* __restrict__ w3, __nv_bfloat16* __restrict__ d3h, __nv_bfloat16* __restrict__ d3l,
    const float* __restrict__ w4, __nv_bfloat16* __restrict__ d4h, __nv_bfloat16* __restrict__ d4l,
    const float* __restrict__ w5, __nv_bfloat16* __restrict__ d5h, __nv_bfloat16* __restrict__ d5l)
{
    const int bx = blockIdx.x;
    const int tid = threadIdx.x;
    if (bx < NB_CHWN) {
        extern __shared__ float s[];
        const int half = bx & 1;
        const int r = bx >> 1;
        const int ih = r % 227, ci = r / 227;
        const int off = half * 114;
        const int W = half ? 113 : 114;
        for (int i = tid; i < W*64; i += 256) {
            const int n = i / W, iw = i % W;
            s[iw*65 + n] = x[(((size_t)n*3 + ci)*227 + ih)*227 + off + iw];
        }
        __syncthreads();
        for (int i = tid; i < W*64; i += 256) {
            const int iw = i >> 6, n = i & 63;
            const float v = s[iw*65 + n];
            const __nv_bfloat16 hv = __float2bfloat16(v);
            const __nv_bfloat16 lv = __float2bfloat16(v - __bfloat162float(hv));
            const size_t o = (((size_t)ci*227 + ih)*227 + off + iw)*64 + n;
            c1h[o] = hv; c1l[o] = lv;
        }
        return;
    }
    if (bx < NB_CHWN + NB_ZERO) {
        const uint4 zv = make_uint4(0,0,0,0);
        const size_t idx = (size_t)(bx - NB_CHWN)*256 + tid;
        const size_t s2 = 761856, s3 = 491520, s4 = 737280;
        if (idx < s2) { za[idx] = zv; zb4[idx] = zv; }
        if (idx < s3) { zc[idx] = zv; zd[idx] = zv; }
        if (idx < s4) { ze[idx] = zv; zf[idx] = zv; zg[idx] = zv; zh[idx] = zv; }
        if (idx < 8)  { zz[idx] = zv; }
        return;
    }
    int idx = (bx - NB_CHWN - NB_ZERO)*256 + tid;
    if (idx >= NPREP) return;
    if (idx < 36864) {
        const int e = idx % 3072, kb = idx / 3072;
        const int co = e >> 5, kk = e & 31;
        const int k = kb*32 + kk;
        float val = 0.f;
        if (k < 363) {
            const int tap = k/3, ci = k%3;
            val = w1[((size_t)(co*3 + ci)*11 + tap/11)*11 + tap%11];
        }
        const __nv_bfloat16 hv = __float2bfloat16(val);
        const __nv_bfloat16 lv = __float2bfloat16(val - __bfloat162float(hv));
        const size_t o = (size_t)kb*3072 + co*32 + (kk ^ ((co & 3) << 3));
        d1h[o] = hv; d1l[o] = lv;
        return;
    }
    idx -= 36864;
    if (idx < 150*4096) { prep_generic(w2, d2h, d2l,  96, 25,  3,  75, idx); return; }
    idx -= 150*4096;
    if (idx < 216*4096) { prep_generic(w3, d3h, d3l, 256,  9,  8,  72, idx); return; }
    idx -= 216*4096;
    if (idx < 324*4096) { prep_generic(w4, d4h, d4l, 384,  9, 12, 108, idx); return; }
    idx -= 324*4096;
    prep_generic(w5, d5h, d5l, 384,  9, 12, 108, idx);
}

// ---------------- pools (CHWN) ----------------
__global__ void pool1_chwn(const float* __restrict__ x, __nv_bfloat16* __restrict__ dh,
                           __nv_bfloat16* __restrict__ dl, int total)
{
    int idx = blockIdx.x * blockDim.x + threadIdx.x;
    if (idx >= total) return;
    const int n = idx & 63;
    int r = idx >> 6;
    const int ow = r % 27; r /= 27;
    const int oh = r % 27; r /= 27;
    const int co = r;
    float s = 0.f;
    #pragma unroll
    for (int i = 0; i < 3; ++i)
        #pragma unroll
        for (int j = 0; j < 3; ++j)
            s += x[(((size_t)co*55 + (oh*2 + i))*55 + (ow*2 + j))*64 + n];
    const float v = s * (1.0f/9.0f);
    const __nv_bfloat16 hv = __float2bfloat16(v);
    const __nv_bfloat16 lv = __float2bfloat16(v - __bfloat162float(hv));
    const size_t o = (((size_t)co*31 + oh + 2)*32 + ow + 2)*64 + n;
    dh[o] = hv; dl[o] = lv;
}

__global__ void pool2_chwn(const float* __restrict__ x, __nv_bfloat16* __restrict__ dh,
                           __nv_bfloat16* __restrict__ dl, int total)
{
    int idx = blockIdx.x * blockDim.x + threadIdx.x;
    if (idx >= total) return;
    const int n = idx & 63;
    int r = idx >> 6;
    const int ow = r % 13; r /= 13;
    const int oh = r % 13; r /= 13;
    const int co = r;
    float s = 0.f;
    #pragma unroll
    for (int i = 0; i < 3; ++i)
        #pragma unroll
        for (int j = 0; j < 3; ++j)
            s += x[(((size_t)co*27 + (oh*2 + i))*27 + (ow*2 + j))*64 + n];
    const float v = s * (1.0f/9.0f);
    const __nv_bfloat16 hv = __float2bfloat16(v);
    const __nv_bfloat16 lv = __float2bfloat16(v - __bfloat162float(hv));
    const size_t o = (((size_t)co*15 + oh + 1)*16 + ow + 1)*64 + n;
    dh[o] = hv; dl[o] = lv;
}

__global__ void pool3_chwn(const float* __restrict__ x, float* __restrict__ y, int total)
{
    int idx = blockIdx.x * blockDim.x + threadIdx.x;
    if (idx >= total) return;
    const int n = idx & 63;
    int r = idx >> 6;
    const int ow = r % 6; r /= 6;
    const int oh = r % 6; r /= 6;
    const int co = r;
    float s = 0.f;
    #pragma unroll
    for (int i = 0; i < 3; ++i)
        #pragma unroll
        for (int j = 0; j < 3; ++j)
            s += x[(((size_t)co*13 + (oh*2 + i))*13 + (ow*2 + j))*64 + n];
    y[(size_t)n*9216 + co*36 + oh*6 + ow] = s * (1.0f/9.0f);
}

// ---------------- FC scalar (fc3 only) ----------------
__global__ __launch_bounds__(128) void fc_big(
    const float* __restrict__ x, const float* __restrict__ w,
    float* __restrict__ part, int K, int N, int S)
{
    const int n = blockIdx.x*128 + threadIdx.x;
    const int s = blockIdx.z;
    const int kc = K / S;
    const int k0 = s*kc, k1 = k0 + kc;
    const int tid = threadIdx.x;

    __shared__ __align__(16) float xs[32][66];
    unsigned long long acc2[32];
    #pragma unroll
    for (int i = 0; i < 32; ++i) acc2[i] = 0ull;

    for (int kt = k0; kt < k1; kt += 32) {
        __syncthreads();
        for (int i = tid; i < 2048; i += 128) {
            const int kk = i & 31, m = i >> 5;
            xs[kk][m] = x[(size_t)m*K + kt + kk];
        }
        __syncthreads();
        if (n < N) {
            #pragma unroll 4
            for (int kk = 0; kk < 32; ++kk) {
                const float wv = w[(size_t)(kt + kk)*N + n];
                const unsigned long long wp = pk2(wv, wv);
                #pragma unroll
                for (int mp = 0; mp < 32; ++mp)
                    fma2(acc2[mp], *(const unsigned long long*)&xs[kk][2*mp], wp);
            }
        }
    }
    if (n < N) {
        #pragma unroll
        for (int mp = 0; mp < 32; ++mp) {
            float v0, v1;
            upk2(v0, v1, acc2[mp]);
            part[((size_t)s*64 + 2*mp    )*N + n] = v0;
            part[((size_t)s*64 + 2*mp + 1)*N + n] = v1;
        }
    }
}

__global__ void fc_reduce(const float* __restrict__ part, const float* __restrict__ bias,
                          float* __restrict__ out, int N, int S, int total)
{
    int idx = blockIdx.x*blockDim.x + threadIdx.x;
    if (idx >= total) return;
    int n = idx % N;
    float s = bias[n];
    for (int i = 0; i < S; ++i) s += part[(size_t)i*64*N + idx];
    out[idx] = s;
}

// ---------------- host launcher ----------------
extern "C" void kernel_launch(void* const* d_in, const int* in_sizes, int n_in,
                              void* d_out, int out_size)
{
    const float* x   = (const float*)d_in[0];
    const float* w1  = (const float*)d_in[1];
    const float* b1  = (const float*)d_in[2];
    const float* w2  = (const float*)d_in[3];
    const float* b2  = (const float*)d_in[4];
    const float* w3  = (const float*)d_in[5];
    const float* b3  = (const float*)d_in[6];
    const float* w4  = (const float*)d_in[7];
    const float* b4  = (const float*)d_in[8];
    const float* w5  = (const float*)d_in[9];
    const float* b5  = (const float*)d_in[10];
    const float* fw1 = (const float*)d_in[11];
    const float* fb1 = (const float*)d_in[12];
    const float* fw2 = (const float*)d_in[13];
    const float* fb2 = (const float*)d_in[14];
    const float* fw3 = (const float*)d_in[15];
    const float* fb3 = (const float*)d_in[16];
    float* out = (float*)d_out;

    float *a1t,*a2t,*a5t,*p3,*f1,*f2,*part;
    __nv_bfloat16 *zb,*xc1h,*xc1l,*xt2h,*xt2l,*xt3h,*xt3l,*xt4h,*xt4l,*xt5h,*xt5l;
    __nv_bfloat16 *w1h,*w1l,*w2h,*w2l,*w3h,*w3l,*w4h,*w4l,*w5h,*w5l;
    cudaGetSymbolAddress((void**)&a1t, g_a1t);
    cudaGetSymbolAddress((void**)&a2t, g_a2t);
    cudaGetSymbolAddress((void**)&a5t, g_a5t);
    cudaGetSymbolAddress((void**)&p3, g_p3);
    cudaGetSymbolAddress((void**)&f1, g_f1);
    cudaGetSymbolAddress((void**)&f2, g_f2);
    cudaGetSymbolAddress((void**)&part, g_part);
    cudaGetSymbolAddress((void**)&zb, g_zero);
    cudaGetSymbolAddress((void**)&xc1h, g_xc1h);
    cudaGetSymbolAddress((void**)&xc1l, g_xc1l);
    cudaGetSymbolAddress((void**)&xt2h, g_xt2h);
    cudaGetSymbolAddress((void**)&xt2l, g_xt2l);
    cudaGetSymbolAddress((void**)&xt3h, g_xt3h);
    cudaGetSymbolAddress((void**)&xt3l, g_xt3l);
    cudaGetSymbolAddress((void**)&xt4h, g_xt4h);
    cudaGetSymbolAddress((void**)&xt4l, g_xt4l);
    cudaGetSymbolAddress((void**)&xt5h, g_xt5h);
    cudaGetSymbolAddress((void**)&xt5l, g_xt5l);
    cudaGetSymbolAddress((void**)&w1h, g_w1h);
    cudaGetSymbolAddress((void**)&w1l, g_w1l);
    cudaGetSymbolAddress((void**)&w2h, g_w2h);
    cudaGetSymbolAddress((void**)&w2l, g_w2l);
    cudaGetSymbolAddress((void**)&w3h, g_w3h);
    cudaGetSymbolAddress((void**)&w3l, g_w3l);
    cudaGetSymbolAddress((void**)&w4h, g_w4h);
    cudaGetSymbolAddress((void**)&w4l, g_w4l);
    cudaGetSymbolAddress((void**)&w5h, g_w5h);
    cudaGetSymbolAddress((void**)&w5l, g_w5l);

    cudaFuncSetAttribute(mconv1,               cudaFuncAttributeMaxDynamicSharedMemorySize, 86016);
    cudaFuncSetAttribute(mconv2<96,5,27,2,0>,  cudaFuncAttributeMaxDynamicSharedMemorySize, 98304);
    cudaFuncSetAttribute(mconv2<256,3,13,1,1>, cudaFuncAttributeMaxDynamicSharedMemorySize, 98304);
    cudaFuncSetAttribute(mconv2<384,3,13,1,1>, cudaFuncAttributeMaxDynamicSharedMemorySize, 98304);
    cudaFuncSetAttribute(mconv2<384,3,13,1,0>, cudaFuncAttributeMaxDynamicSharedMemorySize, 98304);

    // 1: fused setup
    setup_all<<<NB_CHWN + NB_ZERO + NB_PREP, 256, 114*65*4>>>(
        x, xc1h, xc1l,
        (uint4*)xt2h, (uint4*)xt2l, (uint4*)xt3h, (uint4*)xt3l,
        (uint4*)xt4h, (uint4*)xt4l, (uint4*)xt5h, (uint4*)xt5l, (uint4*)zb,
        w1, w1h, w1l, w2, w2h, w2l, w3, w3h, w3l, w4, w4h, w4l, w5, w5h, w5l);
    // 2: conv1
    mconv1<<<dim3(55*28), 192, 86016>>>(xc1h, xc1l, w1h, w1l, b1, zb, a1t);
    // 3: pool1
    { int t = 96*27*27*64; pool1_chwn<<<(t+255)/256, 256>>>(a1t, xt2h, xt2l, t); }
    // 4: conv2 (profiled launch)
    mconv2<96,5,27,2,0><<<dim3(27*14, 2), 256, 98304>>>(xt2h, xt2l, w2h, w2l, b2, nullptr, nullptr, a2t);
    // 5: pool2
    { int t = 256*13*13*64; pool2_chwn<<<(t+255)/256, 256>>>(a2t, xt3h, xt3l, t); }
    // conv3/4/5
    mconv2<256,3,13,1,1><<<dim3(13*7, 3), 256, 98304>>>(xt3h, xt3l, w3h, w3l, b3, xt4h, xt4l, nullptr);
    mconv2<384,3,13,1,1><<<dim3(13*7, 3), 256, 98304>>>(xt4h, xt4l, w4h, w4l, b4, xt5h, xt5l, nullptr);
    mconv2<384,3,13,1,0><<<dim3(13*7, 2), 256, 98304>>>(xt5h, xt5l, w5h, w5l, b5, nullptr, nullptr, a5t);
    // pool3
    { int t = 64*256*36; pool3_chwn<<<(t+255)/256, 256>>>(a5t, p3, t); }

    // FC (fc1/fc2 on tensor cores, fc3 scalar)
    fc_mma<<<dim3(32, 8), 256>>>(p3, fw1, part, 9216, 4096, 8);
    fc_reduce<<<(64*4096 + 255)/256, 256>>>(part, fb1, f1, 4096, 8, 64*4096);
    fc_mma<<<dim3(32, 8), 256>>>(f1, fw2, part, 4096, 4096, 8);
    fc_reduce<<<(64*4096 + 255)/256, 256>>>(part, fb2, f2, 4096, 8, 64*4096);
    fc_big<<<dim3(8, 1, 8), 128>>>(f2, fw3, part, 4096, 1000, 8);
    fc_reduce<<<(64*1000 + 255)/256, 256>>>(part, fb3, out, 1000, 8, 64*1000);
}

// round 17
// speedup vs baseline: 1.6055x; 1.1146x over previous
#include <cuda_runtime.h>
#include <cuda_bf16.h>
#include <cstddef>
#include <cstdint>

// ---------------- scratch ----------------
__device__ __align__(16) float g_a1t[96*55*55*64];
__device__ __align__(16) float g_a2t[256*27*27*64];
__device__ __align__(16) float g_a5t[256*13*13*64];
__device__ __align__(16) float g_p3[64*256*6*6];
__device__ __align__(16) float g_part[8*64*4096];
__device__ __align__(16) float g_part2[8*64*4096];
__device__ __align__(16) __nv_bfloat16 g_zero[64];

// CHWN split-bf16 activations
__device__ __align__(16) __nv_bfloat16 g_xc1h[3*227*227*64];
__device__ __align__(16) __nv_bfloat16 g_xc1l[3*227*227*64];
__device__ __align__(16) __nv_bfloat16 g_xt2h[96*31*32*64];
__device__ __align__(16) __nv_bfloat16 g_xt2l[96*31*32*64];
__device__ __align__(16) __nv_bfloat16 g_xt3h[256*15*16*64];
__device__ __align__(16) __nv_bfloat16 g_xt3l[256*15*16*64];
__device__ __align__(16) __nv_bfloat16 g_xt4h[384*15*16*64];
__device__ __align__(16) __nv_bfloat16 g_xt4l[384*15*16*64];
__device__ __align__(16) __nv_bfloat16 g_xt5h[384*15*16*64];
__device__ __align__(16) __nv_bfloat16 g_xt5l[384*15*16*64];
// pre-packed swizzled weight A-tiles
__device__ __align__(16) __nv_bfloat16 g_w1h[12*3072];
__device__ __align__(16) __nv_bfloat16 g_w1l[12*3072];
__device__ __align__(16) __nv_bfloat16 g_w2h[2*75*4096];
__device__ __align__(16) __nv_bfloat16 g_w2l[2*75*4096];
__device__ __align__(16) __nv_bfloat16 g_w3h[3*72*4096];
__device__ __align__(16) __nv_bfloat16 g_w3l[3*72*4096];
__device__ __align__(16) __nv_bfloat16 g_w4h[3*108*4096];
__device__ __align__(16) __nv_bfloat16 g_w4l[3*108*4096];
__device__ __align__(16) __nv_bfloat16 g_w5h[2*108*4096];
__device__ __align__(16) __nv_bfloat16 g_w5l[2*108*4096];

// ---------------- helpers ----------------
__device__ __forceinline__ uint32_t smem_u32(const void* p) {
    uint32_t a; asm("{ .reg .u64 t; cvta.to.shared.u64 t, %1; cvt.u32.u64 %0, t; }" : "=r"(a) : "l"(p)); return a;
}
__device__ __forceinline__ void mma_bf16(float* c, const unsigned* a, const unsigned* b) {
    asm volatile("mma.sync.aligned.m16n8k16.row.col.f32.bf16.bf16.f32 "
        "{%0,%1,%2,%3}, {%4,%5,%6,%7}, {%8,%9}, {%0,%1,%2,%3};"
        : "+f"(c[0]), "+f"(c[1]), "+f"(c[2]), "+f"(c[3])
        : "r"(a[0]), "r"(a[1]), "r"(a[2]), "r"(a[3]), "r"(b[0]), "r"(b[1]));
}
__device__ __forceinline__ void ldsm_x4(unsigned* r, uint32_t addr) {
    asm volatile("ldmatrix.sync.aligned.m8n8.x4.shared.b16 {%0,%1,%2,%3}, [%4];"
        : "=r"(r[0]), "=r"(r[1]), "=r"(r[2]), "=r"(r[3]) : "r"(addr));
}
__device__ __forceinline__ void ldsm_x2t(unsigned* r, uint32_t addr) {
    asm volatile("ldmatrix.sync.aligned.m8n8.x2.trans.shared.b16 {%0,%1}, [%2];"
        : "=r"(r[0]), "=r"(r[1]) : "r"(addr));
}
__device__ __forceinline__ uint32_t pack_bf(__nv_bfloat16 lo, __nv_bfloat16 hi) {
    return ((uint32_t)__bfloat16_as_ushort(hi) << 16) | __bfloat16_as_ushort(lo);
}
__device__ __forceinline__ void cp_async16(uint32_t dst, const void* src) {
    asm volatile("cp.async.cg.shared.global [%0], [%1], 16;" :: "r"(dst), "l"(src));
}
#define CP_COMMIT() asm volatile("cp.async.commit_group;" ::: "memory")
#define CP_WAIT1()  asm volatile("cp.async.wait_group 1;" ::: "memory")
__device__ __forceinline__ void split2(float v0, float v1, uint32_t &ph, uint32_t &pl) {
    const __nv_bfloat16 h0 = __float2bfloat16(v0);
    const __nv_bfloat16 h1 = __float2bfloat16(v1);
    const __nv_bfloat16 l0 = __float2bfloat16(v0 - __bfloat162float(h0));
    const __nv_bfloat16 l1 = __float2bfloat16(v1 - __bfloat162float(h1));
    ph = pack_bf(h0, h1); pl = pack_bf(l0, l1);
}

// ================= mma conv v2 (stride-1): 2 px/CTA, 256 thr, 3-stage, 2 CTA/SM =================
template<int CIN, int KS, int H, int PAD, int OUT_XT>
__global__ __launch_bounds__(256, 2) void mconv2(
    const __nv_bfloat16* __restrict__ xh, const __nv_bfloat16* __restrict__ xl,
    const __nv_bfloat16* __restrict__ wh, const __nv_bfloat16* __restrict__ wl,
    const float* __restrict__ bias,
    __nv_bfloat16* __restrict__ oxh, __nv_bfloat16* __restrict__ oxl,
    float* __restrict__ ofp)
{
    extern __shared__ __align__(16) char smem[];
    constexpr int HH = H + 2*PAD;
    constexpr int WP = ((HH + 15)/16)*16;
    constexpr int CB = CIN/32;
    constexpr int NKB = KS*KS*CB;
    constexpr int OWP = (H + 1)/2;

    const int tid = threadIdx.x;
    const int warp = tid >> 5, lane = tid & 31;
    const int wm = warp & 3, wn = warp >> 2;
    const int bx = blockIdx.x;
    const int oh = bx / OWP, ow0 = (bx % OWP)*2;
    const int npx = (ow0 + 1 < H) ? 2 : 1;
    const int cotile = blockIdx.y;
    const uint32_t sb = smem_u32(smem);

    const int sr = tid >> 3, su = tid & 7;
    const uint32_t brow = sr*128 + ((su*16) ^ ((sr & 7) << 4));

    auto stage = [&](int kb, int bb) {
        const uint32_t base = sb + bb*32768;
        const size_t wbase16 = ((size_t)(cotile*NKB + kb)) << 13;
        #pragma unroll
        for (int j = 0; j < 2; ++j) {
            const int c = tid + j*256;
            cp_async16(base + c*16,        (const char*)wh + wbase16 + c*16);
            cp_async16(base + 8192 + c*16, (const char*)wl + wbase16 + c*16);
        }
        const int tap = kb / CB, ci0 = (kb % CB)*32;
        const int kh = tap / KS, kw = tap % KS;
        #pragma unroll
        for (int p = 0; p < 2; ++p) {
            const int ow = (p < npx) ? (ow0 + p) : ow0;
            const size_t src = (((size_t)(ci0 + sr)*HH + oh + kh)*WP + ow + kw)*64 + su*8;
            cp_async16(base + 16384 + p*4096 + brow, xh + src);
            cp_async16(base + 24576 + p*4096 + brow, xl + src);
        }
    };

    float C[2][8][4];
    #pragma unroll
    for (int a = 0; a < 2; ++a)
        #pragma unroll
        for (int b = 0; b < 8; ++b)
            #pragma unroll
            for (int c = 0; c < 4; ++c) C[a][b][c] = 0.f;

    stage(0, 0); CP_COMMIT();
    if (NKB > 1) stage(1, 1);
    CP_COMMIT();

    int bcur = 0, bnext2 = 2;
    for (int kb = 0; kb < NKB; ++kb) {
        CP_WAIT1();
        __syncthreads();
        if (kb + 2 < NKB) stage(kb + 2, bnext2);
        CP_COMMIT();

        const uint32_t bA = sb + bcur*32768;
        const uint32_t bB = bA + 16384 + wn*4096;
        const int q = lane >> 3, rr = lane & 7;
        #pragma unroll
        for (int kc = 0; kc < 2; ++kc) {
            unsigned ah[2][4], al[2][4];
            #pragma unroll
            for (int mt = 0; mt < 2; ++mt) {
                const int row = wm*32 + mt*16 + (q & 1)*8 + rr;
                const uint32_t off = row*64 + ((kc*32 + (q >> 1)*16) ^ ((row & 3) << 4));
                ldsm_x4(ah[mt], bA + off);
                ldsm_x4(al[mt], bA + 8192 + off);
            }
            const int k = kc*16 + (lane & 15);
            #pragma unroll
            for (int nt = 0; nt < 8; ++nt) {
                unsigned bh[2], bl[2];
                const uint32_t off = k*128 + ((nt*16) ^ ((k & 7) << 4));
                ldsm_x2t(bh, bB + off);
                ldsm_x2t(bl, bB + 8192 + off);
                #pragma unroll
                for (int mt = 0; mt < 2; ++mt) {
                    mma_bf16(C[mt][nt], ah[mt], bh);
                    mma_bf16(C[mt][nt], ah[mt], bl);
                    mma_bf16(C[mt][nt], al[mt], bh);
                }
            }
        }
        bcur = (bcur == 2) ? 0 : bcur + 1;
        bnext2 = (bnext2 == 2) ? 0 : bnext2 + 1;
    }

    const int p = wn;
    if (p >= npx) return;
    const int ow = ow0 + p;
    const int g = lane >> 2, tg = lane & 3;
    #pragma unroll
    for (int mt = 0; mt < 2; ++mt) {
        #pragma unroll
        for (int hlf = 0; hlf < 2; ++hlf) {
            const int co = cotile*128 + wm*32 + mt*16 + hlf*8 + g;
            const float vb = bias[co] + 1.0f;
            #pragma unroll
            for (int nt = 0; nt < 8; ++nt) {
                const int n = nt*8 + tg*2;
                float v0 = C[mt][nt][hlf*2 + 0] + vb;
                float v1 = C[mt][nt][hlf*2 + 1] + vb;
                const float s0 = v0*v0, s1 = v1*v1;
                if (OUT_XT) {
                    uint32_t ph, pl;
                    split2(s0, s1, ph, pl);
                    const size_t o = (((size_t)co*HH + (oh + PAD))*WP + (ow + PAD))*64 + n;
                    *(uint32_t*)(oxh + o) = ph;
                    *(uint32_t*)(oxl + o) = pl;
                } else {
                    const size_t o = (((size_t)co*H + oh)*H + ow)*64 + n;
                    *(float2*)(ofp + o) = make_float2(s0, s1);
                }
            }
        }
    }
}

// ================= mma conv5: 1 px/CTA (load balance), CIN=384, 13x13, fp32 CHWN out =================
__global__ __launch_bounds__(256, 2) void mconv5(
    const __nv_bfloat16* __restrict__ xh, const __nv_bfloat16* __restrict__ xl,
    const __nv_bfloat16* __restrict__ wh, const __nv_bfloat16* __restrict__ wl,
    const float* __restrict__ bias, float* __restrict__ ofp)
{
    extern __shared__ __align__(16) char smem[];
    constexpr int CB = 12;
    constexpr int NKB = 108;

    const int tid = threadIdx.x;
    const int warp = tid >> 5, lane = tid & 31;
    const int wm = warp & 3, wn = warp >> 2;
    const int bx = blockIdx.x;
    const int oh = bx / 13, ow0 = bx % 13;
    const int cotile = blockIdx.y;
    const uint32_t sb = smem_u32(smem);

    const int sr = tid >> 3, su = tid & 7;
    const uint32_t brow = sr*128 + ((su*16) ^ ((sr & 7) << 4));

    auto stage = [&](int kb, int bb) {
        const uint32_t base = sb + bb*32768;
        const size_t wbase16 = ((size_t)(cotile*NKB + kb)) << 13;
        #pragma unroll
        for (int j = 0; j < 2; ++j) {
            const int c = tid + j*256;
            cp_async16(base + c*16,        (const char*)wh + wbase16 + c*16);
            cp_async16(base + 8192 + c*16, (const char*)wl + wbase16 + c*16);
        }
        const int tap = kb / CB, ci0 = (kb % CB)*32;
        const int kh = tap / 3, kw = tap % 3;
        const size_t src = (((size_t)(ci0 + sr)*15 + oh + kh)*16 + ow0 + kw)*64 + su*8;
        cp_async16(base + 16384 + brow, xh + src);
        cp_async16(base + 24576 + brow, xl + src);
    };

    float C[2][4][4];
    #pragma unroll
    for (int a = 0; a < 2; ++a)
        #pragma unroll
        for (int b = 0; b < 4; ++b)
            #pragma unroll
            for (int c = 0; c < 4; ++c) C[a][b][c] = 0.f;

    stage(0, 0); CP_COMMIT();
    stage(1, 1); CP_COMMIT();

    int bcur = 0, bnext2 = 2;
    for (int kb = 0; kb < NKB; ++kb) {
        CP_WAIT1();
        __syncthreads();
        if (kb + 2 < NKB) stage(kb + 2, bnext2);
        CP_COMMIT();

        const uint32_t bA = sb + bcur*32768;
        const uint32_t bB = bA + 16384;
        const int q = lane >> 3, rr = lane & 7;
        #pragma unroll
        for (int kc = 0; kc < 2; ++kc) {
            unsigned ah[2][4], al[2][4];
            #pragma unroll
            for (int mt = 0; mt < 2; ++mt) {
                const int row = wm*32 + mt*16 + (q & 1)*8 + rr;
                const uint32_t off = row*64 + ((kc*32 + (q >> 1)*16) ^ ((row & 3) << 4));
                ldsm_x4(ah[mt], bA + off);
                ldsm_x4(al[mt], bA + 8192 + off);
            }
            const int k = kc*16 + (lane & 15);
            #pragma unroll
            for (int nt = 0; nt < 4; ++nt) {
                unsigned bh[2], bl[2];
                const uint32_t off = k*128 + (((wn*64) + nt*16) ^ ((k & 7) << 4));
                ldsm_x2t(bh, bB + off);
                ldsm_x2t(bl, bB + 8192 + off);
                #pragma unroll
                for (int mt = 0; mt < 2; ++mt) {
                    mma_bf16(C[mt][nt], ah[mt], bh);
                    mma_bf16(C[mt][nt], ah[mt], bl);
                    mma_bf16(C[mt][nt], al[mt], bh);
                }
            }
        }
        bcur = (bcur == 2) ? 0 : bcur + 1;
        bnext2 = (bnext2 == 2) ? 0 : bnext2 + 1;
    }

    const int g = lane >> 2, tg = lane & 3;
    #pragma unroll
    for (int mt = 0; mt < 2; ++mt) {
        #pragma unroll
        for (int hlf = 0; hlf < 2; ++hlf) {
            const int co = cotile*128 + wm*32 + mt*16 + hlf*8 + g;
            const float vb = bias[co] + 1.0f;
            #pragma unroll
            for (int nt = 0; nt < 4; ++nt) {
                const int n = wn*32 + nt*8 + tg*2;
                float v0 = C[mt][nt][hlf*2 + 0] + vb;
                float v1 = C[mt][nt][hlf*2 + 1] + vb;
                const size_t o = (((size_t)co*13 + oh)*13 + ow0)*64 + n;
                *(float2*)(ofp + o) = make_float2(v0*v0, v1*v1);
            }
        }
    }
}

// ================= mma conv1: 96 co, 6 warps, 2 px/CTA, 3-stage =================
__global__ __launch_bounds__(192, 2) void mconv1(
    const __nv_bfloat16* __restrict__ xh, const __nv_bfloat16* __restrict__ xl,
    const __nv_bfloat16* __restrict__ wh, const __nv_bfloat16* __restrict__ wl,
    const float* __restrict__ bias, const __nv_bfloat16* __restrict__ zbuf,
    float* __restrict__ ofp)
{
    extern __shared__ __align__(16) char smem[];
    constexpr int NKB = 12;

    const int tid = threadIdx.x;
    const int warp = tid >> 5, lane = tid & 31;
    const int wm = warp % 3, wn = warp / 3;
    const int bx = blockIdx.x;
    const int oh = bx / 28, ow0 = (bx % 28)*2;
    const int npx = (ow0 + 1 < 55) ? 2 : 1;
    const uint32_t sb = smem_u32(smem);

    auto stage = [&](int kb, int bb) {
        const uint32_t base = sb + bb*28672;
        const size_t wbase = (size_t)kb * 6144;
        #pragma unroll
        for (int j = 0; j < 2; ++j) {
            const int c = tid + j*192;
            cp_async16(base + c*16,        (const char*)wh + wbase + c*16);
            cp_async16(base + 6144 + c*16, (const char*)wl + wbase + c*16);
        }
        const int kbase = kb*32;
        for (int c = tid; c < 512; c += 192) {
            const int p = c >> 8, r = c & 255;
            const int kk = r >> 3, u = r & 7;
            const int k = kbase + kk;
            const bool valid = k < 363;
            const int tap = k/3, ci = k%3;
            const int kh = tap/11, kw = tap%11;
            const int ow = (p < npx) ? (ow0 + p) : ow0;
            const __nv_bfloat16 *sh, *sl;
            if (valid) {
                const size_t src = (((size_t)ci*227 + oh*4 + kh)*227 + ow*4 + kw)*64 + u*8;
                sh = xh + src; sl = xl + src;
            } else { sh = zbuf + u*8; sl = zbuf + u*8; }
            const uint32_t dst = p*4096 + kk*128 + ((u*16) ^ ((kk & 7) << 4));
            cp_async16(base + 12288 + dst, sh);
            cp_async16(base + 20480 + dst, sl);
        }
    };

    float C[2][8][4];
    #pragma unroll
    for (int a = 0; a < 2; ++a)
        #pragma unroll
        for (int b = 0; b < 8; ++b)
            #pragma unroll
            for (int c = 0; c < 4; ++c) C[a][b][c] = 0.f;

    stage(0, 0); CP_COMMIT();
    stage(1, 1); CP_COMMIT();

    int bcur = 0, bnext2 = 2;
    for (int kb = 0; kb < NKB; ++kb) {
        CP_WAIT1();
        __syncthreads();
        if (kb + 2 < NKB) stage(kb + 2, bnext2);
        CP_COMMIT();

        const uint32_t bA = sb + bcur*28672;
        const uint32_t bB = bA + 12288 + wn*4096;
        const int q = lane >> 3, rr = lane & 7;
        #pragma unroll
        for (int kc = 0; kc < 2; ++kc) {
            unsigned ah[2][4], al[2][4];
            #pragma unroll
            for (int mt = 0; mt < 2; ++mt) {
                const int row = wm*32 + mt*16 + (q & 1)*8 + rr;
                const uint32_t off = row*64 + ((kc*32 + (q >> 1)*16) ^ ((row & 3) << 4));
                ldsm_x4(ah[mt], bA + off);
                ldsm_x4(al[mt], bA + 6144 + off);
            }
            const int k = kc*16 + (lane & 15);
            #pragma unroll
            for (int nt = 0; nt < 8; ++nt) {
                unsigned bh[2], bl[2];
                const uint32_t off = k*128 + ((nt*16) ^ ((k & 7) << 4));
                ldsm_x2t(bh, bB + off);
                ldsm_x2t(bl, bB + 8192 + off);
                #pragma unroll
                for (int mt = 0; mt < 2; ++mt) {
                    mma_bf16(C[mt][nt], ah[mt], bh);
                    mma_bf16(C[mt][nt], ah[mt], bl);
                    mma_bf16(C[mt][nt], al[mt], bh);
                }
            }
        }
        bcur = (bcur == 2) ? 0 : bcur + 1;
        bnext2 = (bnext2 == 2) ? 0 : bnext2 + 1;
    }

    const int p = wn;
    if (p >= npx) return;
    const int ow = ow0 + p;
    const int g = lane >> 2, tg = lane & 3;
    #pragma unroll
    for (int mt = 0; mt < 2; ++mt) {
        #pragma unroll
        for (int hlf = 0; hlf < 2; ++hlf) {
            const int co = wm*32 + mt*16 + hlf*8 + g;
            const float vb = bias[co] + 1.0f;
            #pragma unroll
            for (int nt = 0; nt < 8; ++nt) {
                const int n = nt*8 + tg*2;
                float v0 = C[mt][nt][hlf*2 + 0] + vb;
                float v1 = C[mt][nt][hlf*2 + 1] + vb;
                const size_t o = (((size_t)co*55 + oh)*55 + ow)*64 + n;
                *(float2*)(ofp + o) = make_float2(v0*v0, v1*v1);
            }
        }
    }
}

// ================= FC via mma: C[64m x 128n]/CTA, K/S split, optional fused reduce-in-load, N guard =================
__global__ __launch_bounds__(256, 2) void fc_mma(
    const float* __restrict__ x, const float* __restrict__ w,
    float* __restrict__ part, int K, int N, int S,
    const float* __restrict__ pin, const float* __restrict__ pbias, int Sin)
{
    __shared__ __align__(16) char smem[24576];
    const int tid = threadIdx.x;
    const int warp = tid >> 5, lane = tid & 31;
    const int wm = warp & 3, wn = warp >> 2;
    const int n0 = blockIdx.x * 128;
    const int s = blockIdx.y;
    const int kc = K / S;
    const int k0 = s * kc;
    const int nkb = kc / 32;
    const uint32_t sb = smem_u32(smem);

    const int am = tid >> 2, ak8 = (tid & 3) * 8;
    const int bk = tid >> 3, bch = tid & 7;
    const int nb0 = n0 + bch * 16;

    const uint32_t adst = (uint32_t)(am * 64) + (((uint32_t)(ak8 * 2)) ^ ((am & 3) << 4));
    const uint32_t bbase = 8192u + (bch >> 2) * 4096u + bk * 128u;
    const uint32_t bsw0 = ((uint32_t)((bch & 3) * 32))      ^ ((bk & 7) << 4);
    const uint32_t bsw1 = ((uint32_t)((bch & 3) * 32 + 16)) ^ ((bk & 7) << 4);

    float xr[8], wr[16];
    auto loadx = [&](int kt) {
        const int col = kt + ak8;
        if (pin == nullptr) {
            const float* xp = x + (size_t)am * K + col;
            #pragma unroll
            for (int j = 0; j < 8; ++j) xr[j] = xp[j];
        } else {
            #pragma unroll
            for (int j = 0; j < 8; ++j) {
                float v = pbias[col + j];
                for (int ss = 0; ss < Sin; ++ss)
                    v += pin[((size_t)ss*64 + am)*K + col + j];
                xr[j] = v;
            }
        }
    };
    auto loadw = [&](int kt) {
        const float* wp = w + (size_t)(kt + bk) * N + nb0;
        if (nb0 + 16 <= N) {
            #pragma unroll
            for (int j = 0; j < 16; ++j) wr[j] = wp[j];
        } else {
            #pragma unroll
            for (int j = 0; j < 16; ++j) wr[j] = (nb0 + j < N) ? wp[j] : 0.f;
        }
    };
    loadx(k0); loadw(k0);

    float C[8][4];
    #pragma unroll
    for (int b = 0; b < 8; ++b)
        #pragma unroll
        for (int c = 0; c < 4; ++c) C[b][c] = 0.f;

    for (int kb = 0; kb < nkb; ++kb) {
        __syncthreads();
        {
            uint32_t ph[4], pl[4];
            #pragma unroll
            for (int j = 0; j < 4; ++j) split2(xr[2*j], xr[2*j+1], ph[j], pl[j]);
            *(uint4*)(smem + adst)        = *(const uint4*)ph;
            *(uint4*)(smem + 4096 + adst) = *(const uint4*)pl;
            uint32_t qh[8], ql[8];
            #pragma unroll
            for (int j = 0; j < 8; ++j) split2(wr[2*j], wr[2*j+1], qh[j], ql[j]);
            *(uint4*)(smem + bbase + bsw0)         = *(const uint4*)qh;
            *(uint4*)(smem + bbase + bsw1)         = *(const uint4*)(qh + 4);
            *(uint4*)(smem + 8192 + bbase + bsw0)  = *(const uint4*)ql;
            *(uint4*)(smem + 8192 + bbase + bsw1)  = *(const uint4*)(ql + 4);
        }
        __syncthreads();
        if (kb + 1 < nkb) { loadx(k0 + (kb+1)*32); loadw(k0 + (kb+1)*32); }
        const int q = lane >> 3, rr = lane & 7;
        #pragma unroll
        for (int kk = 0; kk < 2; ++kk) {
            unsigned ah[4], al[4];
            const int row = wm*16 + (q & 1)*8 + rr;
            const uint32_t off = row*64 + ((kk*32 + (q >> 1)*16) ^ ((row & 3) << 4));
            ldsm_x4(ah, sb + off);
            ldsm_x4(al, sb + 4096 + off);
            const int k = kk*16 + (lane & 15);
            #pragma unroll
            for (int nt = 0; nt < 8; ++nt) {
                unsigned bh[2], bl[2];
                const uint32_t off2 = k*128 + ((nt*16) ^ ((k & 7) << 4));
                ldsm_x2t(bh, sb + 8192 + wn*4096 + off2);
                ldsm_x2t(bl, sb + 16384 + wn*4096 + off2);
                mma_bf16(C[nt], ah, bh);
                mma_bf16(C[nt], ah, bl);
                mma_bf16(C[nt], al, bh);
            }
        }
    }

    const int g = lane >> 2, tg = lane & 3;
    #pragma unroll
    for (int hlf = 0; hlf < 2; ++hlf) {
        const int m = wm*16 + hlf*8 + g;
        #pragma unroll
        for (int nt = 0; nt < 8; ++nt) {
            const int n = n0 + wn*64 + nt*8 + tg*2;
            float* dst = part + ((size_t)s*64 + m)*N + n;
            if (n + 1 < N) { *(float2*)dst = make_float2(C[nt][hlf*2], C[nt][hlf*2+1]); }
            else if (n < N) { dst[0] = C[nt][hlf*2]; }
        }
    }
}

// ---------------- fused setup: chwn227 tiles + zero + weight prep ----------------
__device__ __forceinline__ void prep_generic(
    const float* __restrict__ w, __nv_bfloat16* __restrict__ dh, __nv_bfloat16* __restrict__ dl,
    int CIN, int KS2, int CB, int NKB, int idx)
{
    const int e = idx & 4095;
    const int kb = (idx >> 12) % NKB;
    const int cotile = idx / (NKB * 4096);
    const int co = e >> 5, kk = e & 31;
    const int tap = kb / CB;
    const int ci = (kb % CB)*32 + kk;
    const float val = w[((size_t)(cotile*128 + co)*CIN + ci)*KS2 + tap];
    const __nv_bfloat16 hv = __float2bfloat16(val);
    const __nv_bfloat16 lv = __float2bfloat16(val - __bfloat162float(hv));
    const size_t o = ((size_t)(cotile*NKB + kb) << 12) + co*32 + (kk ^ ((co & 3) << 3));
    dh[o] = hv; dl[o] = lv;
}

static constexpr int NB_CHWN = 1362;
static constexpr int NB_ZERO = 2976;
static constexpr int NPREP   = 36864 + (150+216+324+216)*4096;
static constexpr int NB_PREP = (NPREP + 255)/256;

__global__ __launch_bounds__(256) void setup_all(
    const float* __restrict__ x, __nv_bfloat16* __restrict__ c1h, __nv_bfloat16* __restrict__ c1l,
    uint4* za, uint4* zb4, uint4* zc, uint4* zd, uint4* ze, uint4* zf, uint4* zg, uint4* zh, uint4* zz,
    const float* __restrict__ w1, __nv_bfloat16* __restrict__ d1h, __nv_bfloat16* __restrict__ d1l,
    const float* __restrict__ w2, __nv_bfloat16* __restrict__ d2h, __nv_bfloat16* __restrict__ d2l,
    const float* __restrict__ w3, __nv_bfloat16* __restrict__ d3h, __nv_bfloat16* __restrict__ d3l,
    const float* __restrict__ w4, __nv_bfloat16* __restrict__ d4h, __nv_bfloat16* __restrict__ d4l,
    const float* __restrict__ w5, __nv_bfloat16* __restrict__ d5h, __nv_bfloat16* __restrict__ d5l)
{
    const int bx = blockIdx.x;
    const int tid = threadIdx.x;
    if (bx < NB_CHWN) {
        extern __shared__ float s[];
        const int half = bx & 1;
        const int r = bx >> 1;
        const int ih = r % 227, ci = r / 227;
        const int off = half * 114;
        const int W = half ? 113 : 114;
        for (int i = tid; i < W*64; i += 256) {
            const int n = i / W, iw = i % W;
            s[iw*65 + n] = x[(((size_t)n*3 + ci)*227 + ih)*227 + off + iw];
        }
        __syncthreads();
        for (int i = tid; i < W*64; i += 256) {
            const int iw = i >> 6, n = i & 63;
            const float v = s[iw*65 + n];
            const __nv_bfloat16 hv = __float2bfloat16(v);
            const __nv_bfloat16 lv = __float2bfloat16(v - __bfloat162float(hv));
            const size_t o = (((size_t)ci*227 + ih)*227 + off + iw)*64 + n;
            c1h[o] = hv; c1l[o] = lv;
        }
        return;
    }
    if (bx < NB_CHWN + NB_ZERO) {
        const uint4 zv = make_uint4(0,0,0,0);
        const size_t idx = (size_t)(bx - NB_CHWN)*256 + tid;
        const size_t s2 = 761856, s3 = 491520, s4 = 737280;
        if (idx < s2) { za[idx] = zv; zb4[idx] = zv; }
        if (idx < s3) { zc[idx] = zv; zd[idx] = zv; }
        if (idx < s4) { ze[idx] = zv; zf[idx] = zv; zg[idx] = zv; zh[idx] = zv; }
        if (idx < 8)  { zz[idx] = zv; }
        return;
    }
    int idx = (bx - NB_CHWN - NB_ZERO)*256 + tid;
    if (idx >= NPREP) return;
    if (idx < 36864) {
        const int e = idx % 3072, kb = idx / 3072;
        const int co = e >> 5, kk = e & 31;
        const int k = kb*32 + kk;
        float val = 0.f;
        if (k < 363) {
            const int tap = k/3, ci = k%3;
            val = w1[((size_t)(co*3 + ci)*11 + tap/11)*11 + tap%11];
        }
        const __nv_bfloat16 hv = __float2bfloat16(val);
        const __nv_bfloat16 lv = __float2bfloat16(val - __bfloat162float(hv));
        const size_t o = (size_t)kb*3072 + co*32 + (kk ^ ((co & 3) << 3));
        d1h[o] = hv; d1l[o] = lv;
        return;
    }
    idx -= 36864;
    if (idx < 150*4096) { prep_generic(w2, d2h, d2l,  96, 25,  3,  75, idx); return; }
    idx -= 150*4096;
    if (idx < 216*4096) { prep_generic(w3, d3h, d3l, 256,  9,  8,  72, idx); return; }
    idx -= 216*4096;
    if (idx < 324*4096) { prep_generic(w4, d4h, d4l, 384,  9, 12, 108, idx); return; }
    idx -= 324*4096;
    prep_generic(w5, d5h, d5l, 384,  9, 12, 108, idx);
}

// ---------------- pools (CHWN) ----------------
__global__ void pool1_chwn(const float* __restrict__ x, __nv_bfloat16* __restrict__ dh,
                           __nv_bfloat16* __restrict__ dl, int total)
{
    int idx = blockIdx.x * blockDim.x + threadIdx.x;
    if (idx >= total) return;
    const int n = idx & 63;
    int r = idx >> 6;
    const int ow = r % 27; r /= 27;
    const int oh = r % 27; r /= 27;
    const int co = r;
    float s = 0.f;
    #pragma unroll
    for (int i = 0; i < 3; ++i)
        #pragma unroll
        for (int j = 0; j < 3; ++j)
            s += x[(((size_t)co*55 + (oh*2 + i))*55 + (ow*2 + j))*64 + n];
    const float v = s * (1.0f/9.0f);
    const __nv_bfloat16 hv = __float2bfloat16(v);
    const __nv_bfloat16 lv = __float2bfloat16(v - __bfloat162float(hv));
    const size_t o = (((size_t)co*31 + oh + 2)*32 + ow + 2)*64 + n;
    dh[o] = hv; dl[o] = lv;
}

__global__ void pool2_chwn(const float* __restrict__ x, __nv_bfloat16* __restrict__ dh,
                           __nv_bfloat16* __restrict__ dl, int total)
{
    int idx = blockIdx.x * blockDim.x + threadIdx.x;
    if (idx >= total) return;
    const int n = idx & 63;
    int r = idx >> 6;
    const int ow = r % 13; r /= 13;
    const int oh = r % 13; r /= 13;
    const int co = r;
    float s = 0.f;
    #pragma unroll
    for (int i = 0; i < 3; ++i)
        #pragma unroll
        for (int j = 0; j < 3; ++j)
            s += x[(((size_t)co*27 + (oh*2 + i))*27 + (ow*2 + j))*64 + n];
    const float v = s * (1.0f/9.0f);
    const __nv_bfloat16 hv = __float2bfloat16(v);
    const __nv_bfloat16 lv = __float2bfloat16(v - __bfloat162float(hv));
    const size_t o = (((size_t)co*15 + oh + 1)*16 + ow + 1)*64 + n;
    dh[o] = hv; dl[o] = lv;
}

__global__ void pool3_chwn(const float* __restrict__ x, float* __restrict__ y, int total)
{
    int idx = blockIdx.x * blockDim.x + threadIdx.x;
    if (idx >= total) return;
    const int n = idx & 63;
    int r = idx >> 6;
    const int ow = r % 6; r /= 6;
    const int oh = r % 6; r /= 6;
    const int co = r;
    float s = 0.f;
    #pragma unroll
    for (int i = 0; i < 3; ++i)
        #pragma unroll
        for (int j = 0; j < 3; ++j)
            s += x[(((size_t)co*13 + (oh*2 + i))*13 + (ow*2 + j))*64 + n];
    y[(size_t)n*9216 + co*36 + oh*6 + ow] = s * (1.0f/9.0f);
}

__global__ void fc_reduce(const float* __restrict__ part, const float* __restrict__ bias,
                          float* __restrict__ out, int N, int S, int total)
{
    int idx = blockIdx.x*blockDim.x + threadIdx.x;
    if (idx >= total) return;
    int n = idx % N;
    float s = bias[n];
    for (int i = 0; i < S; ++i) s += part[(size_t)i*64*N + idx];
    out[idx] = s;
}

// ---------------- host launcher ----------------
extern "C" void kernel_launch(void* const* d_in, const int* in_sizes, int n_in,
                              void* d_out, int out_size)
{
    const float* x   = (const float*)d_in[0];
    const float* w1  = (const float*)d_in[1];
    const float* b1  = (const float*)d_in[2];
    const float* w2  = (const float*)d_in[3];
    const float* b2  = (const float*)d_in[4];
    const float* w3  = (const float*)d_in[5];
    const float* b3  = (const float*)d_in[6];
    const float* w4  = (const float*)d_in[7];
    const float* b4  = (const float*)d_in[8];
    const float* w5  = (const float*)d_in[9];
    const float* b5  = (const float*)d_in[10];
    const float* fw1 = (const float*)d_in[11];
    const float* fb1 = (const float*)d_in[12];
    const float* fw2 = (const float*)d_in[13];
    const float* fb2 = (const float*)d_in[14];
    const float* fw3 = (const float*)d_in[15];
    const float* fb3 = (const float*)d_in[16];
    float* out = (float*)d_out;

    float *a1t,*a2t,*a5t,*p3,*part,*part2;
    __nv_bfloat16 *zb,*xc1h,*xc1l,*xt2h,*xt2l,*xt3h,*xt3l,*xt4h,*xt4l,*xt5h,*xt5l;
    __nv_bfloat16 *w1h,*w1l,*w2h,*w2l,*w3h,*w3l,*w4h,*w4l,*w5h,*w5l;
    cudaGetSymbolAddress((void**)&a1t, g_a1t);
    cudaGetSymbolAddress((void**)&a2t, g_a2t);
    cudaGetSymbolAddress((void**)&a5t, g_a5t);
    cudaGetSymbolAddress((void**)&p3, g_p3);
    cudaGetSymbolAddress((void**)&part, g_part);
    cudaGetSymbolAddress((void**)&part2, g_part2);
    cudaGetSymbolAddress((void**)&zb, g_zero);
    cudaGetSymbolAddress((void**)&xc1h, g_xc1h);
    cudaGetSymbolAddress((void**)&xc1l, g_xc1l);
    cudaGetSymbolAddress((void**)&xt2h, g_xt2h);
    cudaGetSymbolAddress((void**)&xt2l, g_xt2l);
    cudaGetSymbolAddress((void**)&xt3h, g_xt3h);
    cudaGetSymbolAddress((void**)&xt3l, g_xt3l);
    cudaGetSymbolAddress((void**)&xt4h, g_xt4h);
    cudaGetSymbolAddress((void**)&xt4l, g_xt4l);
    cudaGetSymbolAddress((void**)&xt5h, g_xt5h);
    cudaGetSymbolAddress((void**)&xt5l, g_xt5l);
    cudaGetSymbolAddress((void**)&w1h, g_w1h);
    cudaGetSymbolAddress((void**)&w1l, g_w1l);
    cudaGetSymbolAddress((void**)&w2h, g_w2h);
    cudaGetSymbolAddress((void**)&w2l, g_w2l);
    cudaGetSymbolAddress((void**)&w3h, g_w3h);
    cudaGetSymbolAddress((void**)&w3l, g_w3l);
    cudaGetSymbolAddress((void**)&w4h, g_w4h);
    cudaGetSymbolAddress((void**)&w4l, g_w4l);
    cudaGetSymbolAddress((void**)&w5h, g_w5h);
    cudaGetSymbolAddress((void**)&w5l, g_w5l);

    cudaFuncSetAttribute(mconv1,               cudaFuncAttributeMaxDynamicSharedMemorySize, 86016);
    cudaFuncSetAttribute(mconv2<96,5,27,2,0>,  cudaFuncAttributeMaxDynamicSharedMemorySize, 98304);
    cudaFuncSetAttribute(mconv2<256,3,13,1,1>, cudaFuncAttributeMaxDynamicSharedMemorySize, 98304);
    cudaFuncSetAttribute(mconv2<384,3,13,1,1>, cudaFuncAttributeMaxDynamicSharedMemorySize, 98304);
    cudaFuncSetAttribute(mconv5,               cudaFuncAttributeMaxDynamicSharedMemorySize, 98304);

    // 1: fused setup
    setup_all<<<NB_CHWN + NB_ZERO + NB_PREP, 256, 114*65*4>>>(
        x, xc1h, xc1l,
        (uint4*)xt2h, (uint4*)xt2l, (uint4*)xt3h, (uint4*)xt3l,
        (uint4*)xt4h, (uint4*)xt4l, (uint4*)xt5h, (uint4*)xt5l, (uint4*)zb,
        w1, w1h, w1l, w2, w2h, w2l, w3, w3h, w3l, w4, w4h, w4l, w5, w5h, w5l);
    // 2: conv1
    mconv1<<<dim3(55*28), 192, 86016>>>(xc1h, xc1l, w1h, w1l, b1, zb, a1t);
    // 3: pool1
    { int t = 96*27*27*64; pool1_chwn<<<(t+255)/256, 256>>>(a1t, xt2h, xt2l, t); }
    // 4: conv2 (profiled launch)
    mconv2<96,5,27,2,0><<<dim3(27*14, 2), 256, 98304>>>(xt2h, xt2l, w2h, w2l, b2, nullptr, nullptr, a2t);
    // 5: pool2
    { int t = 256*13*13*64; pool2_chwn<<<(t+255)/256, 256>>>(a2t, xt3h, xt3l, t); }
    // conv3/4
    mconv2<256,3,13,1,1><<<dim3(13*7, 3), 256, 98304>>>(xt3h, xt3l, w3h, w3l, b3, xt4h, xt4l, nullptr);
    mconv2<384,3,13,1,1><<<dim3(13*7, 3), 256, 98304>>>(xt4h, xt4l, w4h, w4l, b4, xt5h, xt5l, nullptr);
    // conv5 (1 px/CTA for load balance)
    mconv5<<<dim3(169, 2), 256, 98304>>>(xt5h, xt5l, w5h, w5l, b5, a5t);
    // pool3
    { int t = 64*256*36; pool3_chwn<<<(t+255)/256, 256>>>(a5t, p3, t); }

    // FC all on tensor cores; reductions fused into next layer's x-load
    fc_mma<<<dim3(32, 8), 256>>>(p3, fw1, part, 9216, 4096, 8, nullptr, nullptr, 0);
    fc_mma<<<dim3(32, 8), 256>>>(nullptr, fw2, part2, 4096, 4096, 8, part, fb1, 8);
    fc_mma<<<dim3(8, 8), 256>>>(nullptr, fw3, part, 4096, 1000, 8, part2, fb2, 8);
    fc_reduce<<<(64*1000 + 255)/256, 256>>>(part, fb3, out, 1000, 8, 64*1000);
}